// round 2
// baseline (speedup 1.0000x reference)
#include <cuda_runtime.h>

#define BRANCHES 4
#define NB 16
#define CPB 64
#define HGT 80
#define WID 80
#define NPIX 6400
#define NHEADS 8

typedef unsigned long long ull;

__device__ __forceinline__ ull ffma2(ull a, ull b, ull c) {
    ull d;
    asm("fma.rn.f32x2 %0, %1, %2, %3;" : "=l"(d) : "l"(a), "l"(b), "l"(c));
    return d;
}
__device__ __forceinline__ ull dup2(float x) {
    ull r;
    asm("mov.b64 %0, {%1, %1};" : "=l"(r) : "f"(x));
    return r;
}
__device__ __forceinline__ float2 unpk(ull v) {
    float2 f;
    asm("mov.b64 {%0, %1}, %2;" : "=f"(f.x), "=f"(f.y) : "l"(v));
    return f;
}

// ---------------- scratch ----------------------------------------------------
__device__ float g_y  [(size_t)BRANCHES*NB*CPB*NPIX];   // dwconv out [br][b][c][n]
__device__ float g_q  [(size_t)BRANCHES*NB*CPB*NPIX];   // raw q [br][b][h*8+d][n]
__device__ float g_ctx[(size_t)BRANCHES*NB*NHEADS*64];  // ctx [brb][h][d*8+e] (atomic acc)
__device__ float g_qm [(size_t)BRANCHES*NB*CPB];        // per-row max of q
__device__ float g_qs [(size_t)BRANCHES*NB*CPB];        // per-row sum exp(q-m)
__device__ float g_att[(size_t)BRANCHES*NB*CPB*NPIX];   // attention out [brb][o][n']

// ---------------- K0: zero ctx accumulator ----------------------------------
__global__ void zero_ctx_kernel() {
    g_ctx[blockIdx.x * 1024 + threadIdx.x] = 0.f;
}

// ---------------- K1: depthwise conv + bias + residual + relu ---------------
// grid (5 row-tiles, 64 channels, 16 batch), block 320 = 20x16
template<int KS>
__global__ void dwconv_kernel(const float* __restrict__ x,
                              const float* __restrict__ w,
                              const float* __restrict__ bias,
                              int br)
{
    __shared__ float tile[24*88];
    __shared__ float wsm[KS*KS];
    const int b    = blockIdx.z;
    const int c    = blockIdx.y;
    const int row0 = blockIdx.x * 16;
    const int tid  = threadIdx.x;

    if (tid < KS*KS) wsm[tid] = w[c*KS*KS + tid];
    const float bv = bias[c];
    const float* xp = x + ((size_t)b*256 + (size_t)br*64 + c) * NPIX;

    for (int idx = tid; idx < 24*88; idx += 320) {
        int r  = idx / 88, cl = idx % 88;
        int gh = row0 - 4 + r, gw = cl - 4;
        float v = 0.f;
        if (gh >= 0 && gh < HGT && gw >= 0 && gw < WID) v = xp[gh*WID + gw];
        tile[idx] = v;
    }
    __syncthreads();

    const int tx = tid % 20, ty = tid / 20;
    const int col0 = tx * 4;
    constexpr int PAD = KS / 2;
    float a0 = 0.f, a1 = 0.f, a2 = 0.f, a3 = 0.f;
    float win[KS + 3];
    #pragma unroll
    for (int kh = 0; kh < KS; kh++) {
        int base = (ty + 4 - PAD + kh)*88 + col0 + 4 - PAD;
        #pragma unroll
        for (int ww = 0; ww < KS + 3; ww++) win[ww] = tile[base + ww];
        #pragma unroll
        for (int kw = 0; kw < KS; kw++) {
            float wv = wsm[kh*KS + kw];
            a0 += win[kw    ] * wv;
            a1 += win[kw + 1] * wv;
            a2 += win[kw + 2] * wv;
            a3 += win[kw + 3] * wv;
        }
    }
    int cb = (ty + 4)*88 + col0 + 4;
    float* yp = g_y + (((size_t)br*NB + b)*CPB + c)*NPIX + (row0 + ty)*WID + col0;
    yp[0] = fmaxf(a0 + bv + tile[cb + 0], 0.f);
    yp[1] = fmaxf(a1 + bv + tile[cb + 1], 0.f);
    yp[2] = fmaxf(a2 + bv + tile[cb + 2], 0.f);
    yp[3] = fmaxf(a3 + bv + tile[cb + 3], 0.f);
}

// ---------------- K2: qkv GEMM + k-softmax + fused ctx + q scatter ----------
// grid (100 token tiles, 64 br*b), block 256, dyn smem 65536B
__global__ void qkv_kernel(const float* __restrict__ wqkv)
{
    extern __shared__ float sm[];
    float* wq = sm;               // [j=192][c=64] : 12288
    float* ys = sm + 12288;       // [c=64][t=64]  :  4096
    const int tid = threadIdx.x;
    const int brb = blockIdx.y;
    const int n0  = blockIdx.x * 64;

    const float* yp = g_y + (size_t)brb * CPB * NPIX;
    for (int idx = tid; idx < 12288; idx += 256) wq[idx] = wqkv[idx];
    for (int idx = tid; idx < 4096;  idx += 256) {
        int c = idx >> 6, t = idx & 63;
        ys[idx] = yp[(size_t)c*NPIX + n0 + t];
    }
    __syncthreads();

    // GEMM: each thread 8 tokens (4 f32x2 pairs) x 6 output cols
    const int tok = (tid & 7) * 8;
    const int j0  = (tid >> 3) * 6;
    ull acc2[6][4];
    #pragma unroll
    for (int jj = 0; jj < 6; jj++)
        #pragma unroll
        for (int tp = 0; tp < 4; tp++) acc2[jj][tp] = 0ull;

    #pragma unroll 4
    for (int c = 0; c < 64; c++) {
        ulonglong2 p0 = *(const ulonglong2*)&ys[c*64 + tok];
        ulonglong2 p1 = *(const ulonglong2*)&ys[c*64 + tok + 4];
        ull ya2[4] = {p0.x, p0.y, p1.x, p1.y};
        #pragma unroll
        for (int jj = 0; jj < 6; jj++) {
            ull w2 = dup2(wq[(j0 + jj)*64 + c]);
            acc2[jj][0] = ffma2(ya2[0], w2, acc2[jj][0]);
            acc2[jj][1] = ffma2(ya2[1], w2, acc2[jj][1]);
            acc2[jj][2] = ffma2(ya2[2], w2, acc2[jj][2]);
            acc2[jj][3] = ffma2(ya2[3], w2, acc2[jj][3]);
        }
    }
    __syncthreads();   // all reads of wq/ys done before overlay

    // overlay: qk [j=192][t stride 66] = 12672 floats
    float* qk = sm;
    #pragma unroll
    for (int jj = 0; jj < 6; jj++)
        #pragma unroll
        for (int tp = 0; tp < 4; tp++)
            *(ull*)&qk[(j0 + jj)*66 + tok + 2*tp] = acc2[jj][tp];
    __syncthreads();

    // k softmax over head-dim (8), in place
    for (int th = tid; th < 512; th += 256) {
        int t = th & 63, h = th >> 6;
        float kr[8];
        #pragma unroll
        for (int d = 0; d < 8; d++) kr[d] = qk[(64 + h*8 + d)*66 + t];
        float m = kr[0];
        #pragma unroll
        for (int d = 1; d < 8; d++) m = fmaxf(m, kr[d]);
        float e[8]; float s = 0.f;
        #pragma unroll
        for (int d = 0; d < 8; d++) { e[d] = __expf(kr[d] - m); s += e[d]; }
        float inv = 1.f / s;
        #pragma unroll
        for (int d = 0; d < 8; d++) qk[(64 + h*8 + d)*66 + t] = e[d] * inv;
    }
    __syncthreads();

    // fused ctx partial: thread owns (h, d, e-pair); sum over 64 tokens
    {
        int h  = tid >> 5;
        int d  = (tid >> 2) & 7;
        int ep = tid & 3;
        const float* krow  = &qk[(64  + h*8 + d)*66];
        const float* vrow0 = &qk[(128 + h*8 + 2*ep)*66];
        const float* vrow1 = vrow0 + 66;
        float ce0 = 0.f, ce1 = 0.f;
        #pragma unroll 8
        for (int t = 0; t < 64; t++) {
            float kv = krow[t];
            ce0 += kv * vrow0[t];
            ce1 += kv * vrow1[t];
        }
        float* cp = &g_ctx[((size_t)brb*NHEADS + h)*64 + d*8 + 2*ep];
        atomicAdd(cp,     ce0);
        atomicAdd(cp + 1, ce1);
    }

    // q scatter (raw) to [brb][hd][n]
    for (int idx = tid; idx < 4096; idx += 256) {
        int hd = idx >> 6, t = idx & 63;
        g_q[((size_t)brb*64 + hd)*NPIX + n0 + t] = qk[hd*66 + t];
    }
}

// ---------------- K3: per-row q stats (max, sum exp) ------------------------
// grid 4096 rows, block 256
__global__ void qstat_kernel()
{
    __shared__ float red[256];
    const float* p = g_q + (size_t)blockIdx.x * NPIX;
    const int tid = threadIdx.x;

    float m = -1e30f;
    for (int i = tid; i < NPIX; i += 256) m = fmaxf(m, p[i]);
    red[tid] = m; __syncthreads();
    for (int s = 128; s; s >>= 1) { if (tid < s) red[tid] = fmaxf(red[tid], red[tid + s]); __syncthreads(); }
    m = red[0]; __syncthreads();

    float sum = 0.f;
    for (int i = tid; i < NPIX; i += 256) sum += __expf(p[i] - m);
    red[tid] = sum; __syncthreads();
    for (int s = 128; s; s >>= 1) { if (tid < s) red[tid] += red[tid + s]; __syncthreads(); }

    if (tid == 0) { g_qm[blockIdx.x] = m; g_qs[blockIdx.x] = red[0]; }
}

// ---------------- K5: out = softmax(q)@ctx, scrambled reshape, proj, scale --
// grid (200 group-tiles, 64 br*b), block 256
__global__ void attn_out_kernel(const float* __restrict__ wproj,
                                const float* __restrict__ bproj,
                                const float* __restrict__ scale)
{
    __shared__ float wp   [64*68];   // [f][o] padded
    __shared__ float out_s[32*64];   // [g][f]
    __shared__ float p_s  [32*64];   // [g][o]
    __shared__ float ctx_s[64];
    __shared__ float m_s[8];
    const int tid = threadIdx.x;
    const int brb = blockIdx.y;
    const int br  = brb >> 4;
    const int g0  = blockIdx.x * 32;       // n' base; 800 % 32 == 0 -> one head per block
    const int h   = g0 / 800;

    for (int idx = tid; idx < 4096; idx += 256) {
        int o = idx >> 6, f = idx & 63;
        wp[f*68 + o] = wproj[idx];          // wproj[o][f]
    }
    if (tid < 64) {
        int d = tid >> 3;
        float invS = 1.f / g_qs[(size_t)brb*64 + h*8 + d];
        ctx_s[tid] = g_ctx[((size_t)brb*NHEADS + h)*64 + tid] * invS;
    }
    if (tid >= 64 && tid < 72) m_s[tid - 64] = g_qm[(size_t)brb*64 + h*8 + (tid - 64)];
    __syncthreads();

    // Phase A: out[g][i*8+e] = sum_d exp(q[h,d,n]-m_d) * ctx'[d,e]
    {
        int g = tid >> 3, i = tid & 7;
        int np = g0 + g;
        int n0 = (np % 800) * 8;
        const float* qp = g_q + ((size_t)brb*64 + h*8)*NPIX + n0 + i;
        ull oo2[4] = {0ull, 0ull, 0ull, 0ull};
        #pragma unroll
        for (int d = 0; d < 8; d++) {
            float qv = __expf(qp[(size_t)d*NPIX] - m_s[d]);
            ull q2 = dup2(qv);
            #pragma unroll
            for (int e2 = 0; e2 < 4; e2++)
                oo2[e2] = ffma2(q2, *(const ull*)&ctx_s[d*8 + e2*2], oo2[e2]);
        }
        #pragma unroll
        for (int e2 = 0; e2 < 4; e2++)
            *(ull*)&out_s[g*64 + i*8 + e2*2] = oo2[e2];
    }
    __syncthreads();

    // Phase B: p[g][o] = (sum_f out[g][f]*wproj[o][f] + bproj[o]) * scale[br]
    {
        int gp = tid >> 4;
        int o4 = (tid & 15) * 4;
        ull q0[2] = {0ull, 0ull}, q1[2] = {0ull, 0ull};
        #pragma unroll 8
        for (int f = 0; f < 64; f++) {
            ull a0d = dup2(out_s[(2*gp    )*64 + f]);
            ull a1d = dup2(out_s[(2*gp + 1)*64 + f]);
            ulonglong2 w2 = *(const ulonglong2*)&wp[f*68 + o4];
            q0[0] = ffma2(a0d, w2.x, q0[0]); q0[1] = ffma2(a0d, w2.y, q0[1]);
            q1[0] = ffma2(a1d, w2.x, q1[0]); q1[1] = ffma2(a1d, w2.y, q1[1]);
        }
        float scl  = __ldg(&scale[br]);
        float4 bp4 = *(const float4*)&bproj[o4];
        float2 u00 = unpk(q0[0]), u01 = unpk(q0[1]);
        float2 u10 = unpk(q1[0]), u11 = unpk(q1[1]);
        float4 r0, r1;
        r0.x = (u00.x + bp4.x)*scl; r0.y = (u00.y + bp4.y)*scl;
        r0.z = (u01.x + bp4.z)*scl; r0.w = (u01.y + bp4.w)*scl;
        r1.x = (u10.x + bp4.x)*scl; r1.y = (u10.y + bp4.y)*scl;
        r1.z = (u11.x + bp4.z)*scl; r1.w = (u11.y + bp4.w)*scl;
        *(float4*)&p_s[(2*gp    )*64 + o4] = r0;
        *(float4*)&p_s[(2*gp + 1)*64 + o4] = r1;
    }
    __syncthreads();

    float* ap = g_att + (size_t)brb*64*NPIX;
    for (int idx = tid; idx < 64*8; idx += 256) {
        int o = idx >> 3, seg = idx & 7;
        float4 r;
        r.x = p_s[(seg*4 + 0)*64 + o];
        r.y = p_s[(seg*4 + 1)*64 + o];
        r.z = p_s[(seg*4 + 2)*64 + o];
        r.w = p_s[(seg*4 + 3)*64 + o];
        *(float4*)&ap[(size_t)o*NPIX + g0 + seg*4] = r;
    }
}

// ---------------- K6: final 256x256 GEMM over pixels ------------------------
// grid (50 n-tiles, 4 o-tiles, 16 b), block 256; 64o x 128n per block
__global__ void final_kernel(const float* __restrict__ wf,
                             const float* __restrict__ bf,
                             float* __restrict__ out)
{
    __shared__ float a_s[32*68];    // [k][o] padded
    __shared__ float b_s[32*128];   // [k][n]
    const int tid = threadIdx.x;
    const int n0  = blockIdx.x * 128;
    const int o0  = blockIdx.y * 64;
    const int b   = blockIdx.z;

    const int n8 = (tid & 15) * 8, o4 = (tid >> 4) * 4;
    ull acc2[4][4];
    #pragma unroll
    for (int i = 0; i < 4; i++)
        #pragma unroll
        for (int j = 0; j < 4; j++) acc2[i][j] = 0ull;

    for (int kc = 0; kc < 256; kc += 32) {
        for (int idx = tid; idx < 32*64; idx += 256) {
            int o = idx >> 5, k = idx & 31;
            a_s[k*68 + o] = wf[(size_t)(o0 + o)*256 + kc + k];
        }
        for (int idx = tid; idx < 32*128; idx += 256) {
            int k = idx >> 7, n = idx & 127;
            int kk = kc + k;
            b_s[k*128 + n] =
                g_att[(((size_t)(kk >> 6)*NB + b)*64 + (kk & 63))*NPIX + n0 + n];
        }
        __syncthreads();
        #pragma unroll
        for (int k = 0; k < 32; k++) {
            float4 a4 = *(const float4*)&a_s[k*68 + o4];
            ull ad[4] = {dup2(a4.x), dup2(a4.y), dup2(a4.z), dup2(a4.w)};
            ulonglong2 b01 = *(const ulonglong2*)&b_s[k*128 + n8];
            ulonglong2 b23 = *(const ulonglong2*)&b_s[k*128 + n8 + 4];
            ull bv[4] = {b01.x, b01.y, b23.x, b23.y};
            #pragma unroll
            for (int i = 0; i < 4; i++)
                #pragma unroll
                for (int j = 0; j < 4; j++)
                    acc2[i][j] = ffma2(ad[i], bv[j], acc2[i][j]);
        }
        __syncthreads();
    }
    float4 bf4 = *(const float4*)&bf[o0 + o4];
    float bb[4] = {bf4.x, bf4.y, bf4.z, bf4.w};
    #pragma unroll
    for (int i = 0; i < 4; i++) {
        float2 u0 = unpk(acc2[i][0]), u1 = unpk(acc2[i][1]);
        float2 u2 = unpk(acc2[i][2]), u3 = unpk(acc2[i][3]);
        float* op = &out[((size_t)b*256 + o0 + o4 + i)*NPIX + n0 + n8];
        float4 r0 = make_float4(u0.x + bb[i], u0.y + bb[i], u1.x + bb[i], u1.y + bb[i]);
        float4 r1 = make_float4(u2.x + bb[i], u2.y + bb[i], u3.x + bb[i], u3.y + bb[i]);
        *(float4*)op       = r0;
        *(float4*)(op + 4) = r1;
    }
}

// ---------------- launch ------------------------------------------------------
extern "C" void kernel_launch(void* const* d_in, const int* in_sizes, int n_in,
                              void* d_out, int out_size)
{
    const float* x     = (const float*)d_in[0];
    const float* w3    = (const float*)d_in[1];
    const float* b3    = (const float*)d_in[2];
    const float* w5    = (const float*)d_in[3];
    const float* b5    = (const float*)d_in[4];
    const float* w7    = (const float*)d_in[5];
    const float* b7    = (const float*)d_in[6];
    const float* w9    = (const float*)d_in[7];
    const float* b9    = (const float*)d_in[8];
    const float* wqkv  = (const float*)d_in[9];
    const float* wproj = (const float*)d_in[10];
    const float* bproj = (const float*)d_in[11];
    const float* wf    = (const float*)d_in[12];
    const float* bf    = (const float*)d_in[13];
    const float* scale = (const float*)d_in[14];
    float* out = (float*)d_out;

    dim3 gconv(5, 64, 16);
    dwconv_kernel<3><<<gconv, 320>>>(x, w3, b3, 0);
    dwconv_kernel<5><<<gconv, 320>>>(x, w5, b5, 1);
    dwconv_kernel<7><<<gconv, 320>>>(x, w7, b7, 2);
    dwconv_kernel<9><<<gconv, 320>>>(x, w9, b9, 3);

    zero_ctx_kernel<<<32, 1024>>>();

    static bool attr_set = false;
    if (!attr_set) {
        cudaFuncSetAttribute(qkv_kernel,
                             cudaFuncAttributeMaxDynamicSharedMemorySize, 65536);
        attr_set = true;
    }
    qkv_kernel<<<dim3(100, 64), 256, 65536>>>(wqkv);
    qstat_kernel<<<4096, 256>>>();
    attn_out_kernel<<<dim3(200, 64), 256>>>(wproj, bproj, scale);
    final_kernel<<<dim3(50, 4, 16), 256>>>(wf, bf, out);
}

// round 3
// speedup vs baseline: 1.0035x; 1.0035x over previous
#include <cuda_runtime.h>

#define BRANCHES 4
#define NB 16
#define CPB 64
#define HGT 80
#define WID 80
#define NPIX 6400
#define NHEADS 8

typedef unsigned long long ull;

__device__ __forceinline__ ull ffma2(ull a, ull b, ull c) {
    ull d;
    asm("fma.rn.f32x2 %0, %1, %2, %3;" : "=l"(d) : "l"(a), "l"(b), "l"(c));
    return d;
}
__device__ __forceinline__ ull dup2(float x) {
    ull r;
    asm("mov.b64 %0, {%1, %1};" : "=l"(r) : "f"(x));
    return r;
}
__device__ __forceinline__ float2 unpk(ull v) {
    float2 f;
    asm("mov.b64 {%0, %1}, %2;" : "=f"(f.x), "=f"(f.y) : "l"(v));
    return f;
}

// ---------------- scratch ----------------------------------------------------
__device__ float g_y  [(size_t)BRANCHES*NB*CPB*NPIX];      // dwconv out [br][b][c][n]
__device__ float g_q  [(size_t)BRANCHES*NB*CPB*NPIX];      // raw q [br][b][h*8+d][n]
__device__ float g_k  [(size_t)BRANCHES*NB*NHEADS*NPIX*8]; // k (softmaxed) [brb][h][n][d]
__device__ float g_v  [(size_t)BRANCHES*NB*NHEADS*NPIX*8]; // v [brb][h][n][d]
__device__ float g_ctx[(size_t)BRANCHES*NB*NHEADS*64];     // ctx [brb][h][d*8+e]
__device__ float g_qm [(size_t)BRANCHES*NB*CPB];           // per-row max of q
__device__ float g_qs [(size_t)BRANCHES*NB*CPB];           // per-row sum exp(q-m)
__device__ float g_att[(size_t)BRANCHES*NB*CPB*NPIX];      // attention out [brb][o][n']

// ---------------- K1: depthwise conv + bias + residual + relu ---------------
// grid (5 row-tiles, 64 channels, 16 batch), block 320 = 20x16
template<int KS>
__global__ void dwconv_kernel(const float* __restrict__ x,
                              const float* __restrict__ w,
                              const float* __restrict__ bias,
                              int br)
{
    __shared__ float tile[24*88];
    __shared__ float wsm[KS*KS];
    const int b    = blockIdx.z;
    const int c    = blockIdx.y;
    const int row0 = blockIdx.x * 16;
    const int tid  = threadIdx.x;

    if (tid < KS*KS) wsm[tid] = w[c*KS*KS + tid];
    const float bv = bias[c];
    const float* xp = x + ((size_t)b*256 + (size_t)br*64 + c) * NPIX;

    for (int idx = tid; idx < 24*88; idx += 320) {
        int r  = idx / 88, cl = idx % 88;
        int gh = row0 - 4 + r, gw = cl - 4;
        float v = 0.f;
        if (gh >= 0 && gh < HGT && gw >= 0 && gw < WID) v = xp[gh*WID + gw];
        tile[idx] = v;
    }
    __syncthreads();

    const int tx = tid % 20, ty = tid / 20;
    const int col0 = tx * 4;
    constexpr int PAD = KS / 2;
    float a0 = 0.f, a1 = 0.f, a2 = 0.f, a3 = 0.f;
    float win[KS + 3];
    #pragma unroll
    for (int kh = 0; kh < KS; kh++) {
        int base = (ty + 4 - PAD + kh)*88 + col0 + 4 - PAD;
        #pragma unroll
        for (int ww = 0; ww < KS + 3; ww++) win[ww] = tile[base + ww];
        #pragma unroll
        for (int kw = 0; kw < KS; kw++) {
            float wv = wsm[kh*KS + kw];
            a0 += win[kw    ] * wv;
            a1 += win[kw + 1] * wv;
            a2 += win[kw + 2] * wv;
            a3 += win[kw + 3] * wv;
        }
    }
    int cb = (ty + 4)*88 + col0 + 4;
    float* yp = g_y + (((size_t)br*NB + b)*CPB + c)*NPIX + (row0 + ty)*WID + col0;
    yp[0] = fmaxf(a0 + bv + tile[cb + 0], 0.f);
    yp[1] = fmaxf(a1 + bv + tile[cb + 1], 0.f);
    yp[2] = fmaxf(a2 + bv + tile[cb + 2], 0.f);
    yp[3] = fmaxf(a3 + bv + tile[cb + 3], 0.f);
}

// ---------------- K2: qkv GEMM + k-softmax + scatter (R1 version) -----------
// grid (100 token tiles, 64 br*b), block 256, dyn smem 65536B
__global__ void qkv_kernel(const float* __restrict__ wqkv)
{
    extern __shared__ float sm[];
    float* wq = sm;               // 192*64 = 12288 floats
    float* ys = sm + 12288;       // 64*64  =  4096 floats
    const int tid = threadIdx.x;
    const int brb = blockIdx.y;
    const int n0  = blockIdx.x * 64;

    const float* yp = g_y + (size_t)brb * CPB * NPIX;
    for (int idx = tid; idx < 192*64; idx += 256) wq[idx] = wqkv[idx];
    for (int idx = tid; idx < 64*64;  idx += 256) {
        int c = idx >> 6, t = idx & 63;
        ys[idx] = yp[(size_t)c*NPIX + n0 + t];
    }
    __syncthreads();

    const int tok = (tid & 15) * 4;
    const int j0  = (tid >> 4) * 12;
    float acc[12][4];
    #pragma unroll
    for (int jj = 0; jj < 12; jj++) { acc[jj][0]=acc[jj][1]=acc[jj][2]=acc[jj][3]=0.f; }

    for (int c = 0; c < 64; c++) {
        float4 ya = *(const float4*)&ys[c*64 + tok];
        #pragma unroll
        for (int jj = 0; jj < 12; jj++) {
            float wv = wq[(j0 + jj)*64 + c];
            acc[jj][0] += ya.x * wv;
            acc[jj][1] += ya.y * wv;
            acc[jj][2] += ya.z * wv;
            acc[jj][3] += ya.w * wv;
        }
    }
    __syncthreads();   // all reads of wq/ys done before overlay

    float* qkvs = sm;  // 64*193 = 12352 floats, padded stride vs bank conflicts
    #pragma unroll
    for (int jj = 0; jj < 12; jj++)
        #pragma unroll
        for (int i = 0; i < 4; i++)
            qkvs[(tok + i)*193 + j0 + jj] = acc[jj][i];
    __syncthreads();

    // k softmax over head-dim (8) + write k, v
    for (int th = tid; th < 64*NHEADS; th += 256) {
        int t = th & 63, h = th >> 6;
        const float* kr = &qkvs[t*193 + 64 + h*8];
        float m = kr[0];
        #pragma unroll
        for (int d = 1; d < 8; d++) m = fmaxf(m, kr[d]);
        float e[8]; float s = 0.f;
        #pragma unroll
        for (int d = 0; d < 8; d++) { e[d] = __expf(kr[d] - m); s += e[d]; }
        float inv = 1.f / s;
        size_t kb = (((size_t)brb*NHEADS + h)*NPIX + n0 + t)*8;
        float4 k0 = make_float4(e[0]*inv, e[1]*inv, e[2]*inv, e[3]*inv);
        float4 k1 = make_float4(e[4]*inv, e[5]*inv, e[6]*inv, e[7]*inv);
        *(float4*)&g_k[kb]     = k0;
        *(float4*)&g_k[kb + 4] = k1;
        const float* vr = &qkvs[t*193 + 128 + h*8];
        float4 v0 = make_float4(vr[0], vr[1], vr[2], vr[3]);
        float4 v1 = make_float4(vr[4], vr[5], vr[6], vr[7]);
        *(float4*)&g_v[kb]     = v0;
        *(float4*)&g_v[kb + 4] = v1;
    }
    // q scatter (raw; stats later) to [brb][hd][n]
    for (int idx = tid; idx < 64*64; idx += 256) {
        int hd = idx >> 6, t = idx & 63;
        g_q[((size_t)brb*64 + hd)*NPIX + n0 + t] = qkvs[t*193 + hd];
    }
}

// ---------------- K3: per-row q stats (max, sum exp) ------------------------
// grid 4096 rows, block 256
__global__ void qstat_kernel()
{
    __shared__ float red[256];
    const float* p = g_q + (size_t)blockIdx.x * NPIX;
    const int tid = threadIdx.x;

    float m = -1e30f;
    for (int i = tid; i < NPIX; i += 256) m = fmaxf(m, p[i]);
    red[tid] = m; __syncthreads();
    for (int s = 128; s; s >>= 1) { if (tid < s) red[tid] = fmaxf(red[tid], red[tid + s]); __syncthreads(); }
    m = red[0]; __syncthreads();

    float sum = 0.f;
    for (int i = tid; i < NPIX; i += 256) sum += __expf(p[i] - m);
    red[tid] = sum; __syncthreads();
    for (int s = 128; s; s >>= 1) { if (tid < s) red[tid] += red[tid + s]; __syncthreads(); }

    if (tid == 0) { g_qm[blockIdx.x] = m; g_qs[blockIdx.x] = red[0]; }
}

// ---------------- K4: ctx = sum_n k[n,d] * v[n,e] (R1 version) --------------
// grid 512 = br*b*h, block 256
__global__ void ctx_kernel()
{
    const int bh  = blockIdx.x;
    const int tid = threadIdx.x;
    const float* kp = g_k + (size_t)bh * NPIX * 8;
    const float* vp = g_v + (size_t)bh * NPIX * 8;

    float acc[8][8];
    #pragma unroll
    for (int d = 0; d < 8; d++)
        #pragma unroll
        for (int e = 0; e < 8; e++) acc[d][e] = 0.f;

    for (int n = tid; n < NPIX; n += 256) {
        float4 k0 = *(const float4*)&kp[(size_t)n*8];
        float4 k1 = *(const float4*)&kp[(size_t)n*8 + 4];
        float4 v0 = *(const float4*)&vp[(size_t)n*8];
        float4 v1 = *(const float4*)&vp[(size_t)n*8 + 4];
        float kk[8] = {k0.x,k0.y,k0.z,k0.w,k1.x,k1.y,k1.z,k1.w};
        float vv[8] = {v0.x,v0.y,v0.z,v0.w,v1.x,v1.y,v1.z,v1.w};
        #pragma unroll
        for (int d = 0; d < 8; d++)
            #pragma unroll
            for (int e = 0; e < 8; e++) acc[d][e] += kk[d] * vv[e];
    }
    #pragma unroll
    for (int off = 16; off; off >>= 1)
        #pragma unroll
        for (int d = 0; d < 8; d++)
            #pragma unroll
            for (int e = 0; e < 8; e++)
                acc[d][e] += __shfl_down_sync(0xffffffffu, acc[d][e], off);

    __shared__ float red[8][64];
    int lane = tid & 31, wp = tid >> 5;
    if (lane == 0) {
        #pragma unroll
        for (int i = 0; i < 64; i++) red[wp][i] = acc[i >> 3][i & 7];
    }
    __syncthreads();
    if (tid < 64) {
        float s = 0.f;
        #pragma unroll
        for (int w = 0; w < 8; w++) s += red[w][tid];
        g_ctx[(size_t)bh*64 + tid] = s;
    }
}

// ---------------- K5: out = softmax(q)@ctx, scrambled reshape, proj, scale --
// grid (200 group-tiles, 64 br*b), block 256
__global__ void attn_out_kernel(const float* __restrict__ wproj,
                                const float* __restrict__ bproj,
                                const float* __restrict__ scale)
{
    __shared__ float wp   [64*68];   // [f][o] padded
    __shared__ float out_s[32*64];   // [g][f]
    __shared__ float p_s  [32*64];   // [g][o]
    __shared__ float ctx_s[64];
    __shared__ float m_s[8];
    const int tid = threadIdx.x;
    const int brb = blockIdx.y;
    const int br  = brb >> 4;
    const int g0  = blockIdx.x * 32;       // n' base; 800 % 32 == 0 -> one head per block
    const int h   = g0 / 800;

    for (int idx = tid; idx < 4096; idx += 256) {
        int o = idx >> 6, f = idx & 63;
        wp[f*68 + o] = wproj[idx];          // wproj[o][f]
    }
    if (tid < 64) {
        int d = tid >> 3;
        float invS = 1.f / g_qs[(size_t)brb*64 + h*8 + d];
        ctx_s[tid] = g_ctx[((size_t)brb*NHEADS + h)*64 + tid] * invS;
    }
    if (tid >= 64 && tid < 72) m_s[tid - 64] = g_qm[(size_t)brb*64 + h*8 + (tid - 64)];
    __syncthreads();

    // Phase A: out[g][i*8+e] = sum_d exp(q[h,d,n]-m_d) * ctx'[d,e]
    {
        int g = tid >> 3, i = tid & 7;
        int np = g0 + g;
        int n0 = (np % 800) * 8;
        const float* qp = g_q + ((size_t)brb*64 + h*8)*NPIX + n0 + i;
        ull oo2[4] = {0ull, 0ull, 0ull, 0ull};
        #pragma unroll
        for (int d = 0; d < 8; d++) {
            float qv = __expf(qp[(size_t)d*NPIX] - m_s[d]);
            ull q2 = dup2(qv);
            #pragma unroll
            for (int e2 = 0; e2 < 4; e2++)
                oo2[e2] = ffma2(q2, *(const ull*)&ctx_s[d*8 + e2*2], oo2[e2]);
        }
        #pragma unroll
        for (int e2 = 0; e2 < 4; e2++)
            *(ull*)&out_s[g*64 + i*8 + e2*2] = oo2[e2];
    }
    __syncthreads();

    // Phase B: p[g][o] = (sum_f out[g][f]*wproj[o][f] + bproj[o]) * scale[br]
    {
        int gp = tid >> 4;
        int o4 = (tid & 15) * 4;
        ull q0[2] = {0ull, 0ull}, q1[2] = {0ull, 0ull};
        #pragma unroll 8
        for (int f = 0; f < 64; f++) {
            ull a0d = dup2(out_s[(2*gp    )*64 + f]);
            ull a1d = dup2(out_s[(2*gp + 1)*64 + f]);
            ulonglong2 w2 = *(const ulonglong2*)&wp[f*68 + o4];
            q0[0] = ffma2(a0d, w2.x, q0[0]); q0[1] = ffma2(a0d, w2.y, q0[1]);
            q1[0] = ffma2(a1d, w2.x, q1[0]); q1[1] = ffma2(a1d, w2.y, q1[1]);
        }
        float scl  = __ldg(&scale[br]);
        float4 bp4 = *(const float4*)&bproj[o4];
        float2 u00 = unpk(q0[0]), u01 = unpk(q0[1]);
        float2 u10 = unpk(q1[0]), u11 = unpk(q1[1]);
        float4 r0, r1;
        r0.x = (u00.x + bp4.x)*scl; r0.y = (u00.y + bp4.y)*scl;
        r0.z = (u01.x + bp4.z)*scl; r0.w = (u01.y + bp4.w)*scl;
        r1.x = (u10.x + bp4.x)*scl; r1.y = (u10.y + bp4.y)*scl;
        r1.z = (u11.x + bp4.z)*scl; r1.w = (u11.y + bp4.w)*scl;
        *(float4*)&p_s[(2*gp    )*64 + o4] = r0;
        *(float4*)&p_s[(2*gp + 1)*64 + o4] = r1;
    }
    __syncthreads();

    float* ap = g_att + (size_t)brb*64*NPIX;
    for (int idx = tid; idx < 64*8; idx += 256) {
        int o = idx >> 3, seg = idx & 7;
        float4 r;
        r.x = p_s[(seg*4 + 0)*64 + o];
        r.y = p_s[(seg*4 + 1)*64 + o];
        r.z = p_s[(seg*4 + 2)*64 + o];
        r.w = p_s[(seg*4 + 3)*64 + o];
        *(float4*)&ap[(size_t)o*NPIX + g0 + seg*4] = r;
    }
}

// ---------------- K6: final 256x256 GEMM over pixels (f32x2) ----------------
// grid (50 n-tiles, 4 o-tiles, 16 b), block 256; 64o x 128n per block
__global__ void final_kernel(const float* __restrict__ wf,
                             const float* __restrict__ bf,
                             float* __restrict__ out)
{
    __shared__ float a_s[32*68];    // [k][o] padded
    __shared__ float b_s[32*128];   // [k][n]
    const int tid = threadIdx.x;
    const int n0  = blockIdx.x * 128;
    const int o0  = blockIdx.y * 64;
    const int b   = blockIdx.z;

    const int n8 = (tid & 15) * 8, o4 = (tid >> 4) * 4;
    ull acc2[4][4];
    #pragma unroll
    for (int i = 0; i < 4; i++)
        #pragma unroll
        for (int j = 0; j < 4; j++) acc2[i][j] = 0ull;

    for (int kc = 0; kc < 256; kc += 32) {
        for (int idx = tid; idx < 32*64; idx += 256) {
            int o = idx >> 5, k = idx & 31;
            a_s[k*68 + o] = wf[(size_t)(o0 + o)*256 + kc + k];
        }
        for (int idx = tid; idx < 32*128; idx += 256) {
            int k = idx >> 7, n = idx & 127;
            int kk = kc + k;
            b_s[k*128 + n] =
                g_att[(((size_t)(kk >> 6)*NB + b)*64 + (kk & 63))*NPIX + n0 + n];
        }
        __syncthreads();
        #pragma unroll
        for (int k = 0; k < 32; k++) {
            float4 a4 = *(const float4*)&a_s[k*68 + o4];
            ull ad[4] = {dup2(a4.x), dup2(a4.y), dup2(a4.z), dup2(a4.w)};
            ulonglong2 b01 = *(const ulonglong2*)&b_s[k*128 + n8];
            ulonglong2 b23 = *(const ulonglong2*)&b_s[k*128 + n8 + 4];
            ull bv[4] = {b01.x, b01.y, b23.x, b23.y};
            #pragma unroll
            for (int i = 0; i < 4; i++)
                #pragma unroll
                for (int j = 0; j < 4; j++)
                    acc2[i][j] = ffma2(ad[i], bv[j], acc2[i][j]);
        }
        __syncthreads();
    }
    float4 bf4 = *(const float4*)&bf[o0 + o4];
    float bb[4] = {bf4.x, bf4.y, bf4.z, bf4.w};
    #pragma unroll
    for (int i = 0; i < 4; i++) {
        float2 u0 = unpk(acc2[i][0]), u1 = unpk(acc2[i][1]);
        float2 u2 = unpk(acc2[i][2]), u3 = unpk(acc2[i][3]);
        float* op = &out[((size_t)b*256 + o0 + o4 + i)*NPIX + n0 + n8];
        float4 r0 = make_float4(u0.x + bb[i], u0.y + bb[i], u1.x + bb[i], u1.y + bb[i]);
        float4 r1 = make_float4(u2.x + bb[i], u2.y + bb[i], u3.x + bb[i], u3.y + bb[i]);
        *(float4*)op       = r0;
        *(float4*)(op + 4) = r1;
    }
}

// ---------------- launch ------------------------------------------------------
extern "C" void kernel_launch(void* const* d_in, const int* in_sizes, int n_in,
                              void* d_out, int out_size)
{
    const float* x     = (const float*)d_in[0];
    const float* w3    = (const float*)d_in[1];
    const float* b3    = (const float*)d_in[2];
    const float* w5    = (const float*)d_in[3];
    const float* b5    = (const float*)d_in[4];
    const float* w7    = (const float*)d_in[5];
    const float* b7    = (const float*)d_in[6];
    const float* w9    = (const float*)d_in[7];
    const float* b9    = (const float*)d_in[8];
    const float* wqkv  = (const float*)d_in[9];
    const float* wproj = (const float*)d_in[10];
    const float* bproj = (const float*)d_in[11];
    const float* wf    = (const float*)d_in[12];
    const float* bf    = (const float*)d_in[13];
    const float* scale = (const float*)d_in[14];
    float* out = (float*)d_out;

    dim3 gconv(5, 64, 16);
    dwconv_kernel<3><<<gconv, 320>>>(x, w3, b3, 0);
    dwconv_kernel<5><<<gconv, 320>>>(x, w5, b5, 1);
    dwconv_kernel<7><<<gconv, 320>>>(x, w7, b7, 2);
    dwconv_kernel<9><<<gconv, 320>>>(x, w9, b9, 3);

    static bool attr_set = false;
    if (!attr_set) {
        cudaFuncSetAttribute(qkv_kernel,
                             cudaFuncAttributeMaxDynamicSharedMemorySize, 65536);
        attr_set = true;
    }
    qkv_kernel<<<dim3(100, 64), 256, 65536>>>(wqkv);
    qstat_kernel<<<4096, 256>>>();
    ctx_kernel<<<512, 256>>>();
    attn_out_kernel<<<dim3(200, 64), 256>>>(wproj, bproj, scale);
    final_kernel<<<dim3(50, 4, 16), 256>>>(wf, bf, out);
}

// round 4
// speedup vs baseline: 1.1046x; 1.1008x over previous
#include <cuda_runtime.h>

#define BRANCHES 4
#define NB 16
#define CPB 64
#define HGT 80
#define WID 80
#define NPIX 6400
#define NHEADS 8
#define NTILES 100

// ---------------- scratch ----------------------------------------------------
__device__ float g_y    [(size_t)BRANCHES*NB*CPB*NPIX];   // dwconv out [brb][c][n]
__device__ float g_q    [(size_t)BRANCHES*NB*CPB*NPIX];   // raw q [brb][h*8+d][n]
__device__ float g_ctx  [(size_t)BRANCHES*NB*NHEADS*64];  // ctx [brb][h][d*8+e]
__device__ float g_cpart[(size_t)NTILES*64*512];          // partial ctx [tile][brb][h*64+cell]
__device__ float g_pm   [(size_t)4096*NTILES];            // per-tile q max [row][tile]
__device__ float g_ps   [(size_t)4096*NTILES];            // per-tile q sumexp [row][tile]
__device__ float g_qm   [(size_t)4096];                   // global q max per row
__device__ float g_qs   [(size_t)4096];                   // global q sumexp per row
__device__ float g_att  [(size_t)BRANCHES*NB*CPB*NPIX];   // attention out [brb][o][n']

// ---------------- K1: depthwise conv + bias + residual + relu ---------------
// grid (5 row-tiles, 64 channels, 16 batch), block 320 = 20x16
template<int KS>
__global__ void dwconv_kernel(const float* __restrict__ x,
                              const float* __restrict__ w,
                              const float* __restrict__ bias,
                              int br)
{
    __shared__ float tile[24*88];
    __shared__ float wsm[KS*KS];
    const int b    = blockIdx.z;
    const int c    = blockIdx.y;
    const int row0 = blockIdx.x * 16;
    const int tid  = threadIdx.x;

    if (tid < KS*KS) wsm[tid] = w[c*KS*KS + tid];
    const float bv = bias[c];
    const float* xp = x + ((size_t)b*256 + (size_t)br*64 + c) * NPIX;

    for (int idx = tid; idx < 24*88; idx += 320) {
        int r  = idx / 88, cl = idx % 88;
        int gh = row0 - 4 + r, gw = cl - 4;
        float v = 0.f;
        if (gh >= 0 && gh < HGT && gw >= 0 && gw < WID) v = xp[gh*WID + gw];
        tile[idx] = v;
    }
    __syncthreads();

    const int tx = tid % 20, ty = tid / 20;
    const int col0 = tx * 4;
    constexpr int PAD = KS / 2;
    float a0 = 0.f, a1 = 0.f, a2 = 0.f, a3 = 0.f;
    float win[KS + 3];
    #pragma unroll
    for (int kh = 0; kh < KS; kh++) {
        int base = (ty + 4 - PAD + kh)*88 + col0 + 4 - PAD;
        #pragma unroll
        for (int ww = 0; ww < KS + 3; ww++) win[ww] = tile[base + ww];
        #pragma unroll
        for (int kw = 0; kw < KS; kw++) {
            float wv = wsm[kh*KS + kw];
            a0 += win[kw    ] * wv;
            a1 += win[kw + 1] * wv;
            a2 += win[kw + 2] * wv;
            a3 += win[kw + 3] * wv;
        }
    }
    int cb = (ty + 4)*88 + col0 + 4;
    float* yp = g_y + (((size_t)br*NB + b)*CPB + c)*NPIX + (row0 + ty)*WID + col0;
    yp[0] = fmaxf(a0 + bv + tile[cb + 0], 0.f);
    yp[1] = fmaxf(a1 + bv + tile[cb + 1], 0.f);
    yp[2] = fmaxf(a2 + bv + tile[cb + 2], 0.f);
    yp[3] = fmaxf(a3 + bv + tile[cb + 3], 0.f);
}

// ---------------- K2: qkv GEMM + k-softmax + partial ctx + partial q stats --
// grid (100 token tiles, 64 br*b), block 256, dyn smem 65536B
#define QSTR 194    // qkvs token stride (even -> 8B-aligned float2 access)
__global__ void qkv_kernel(const float* __restrict__ wqkv)
{
    extern __shared__ float sm[];
    float* wq = sm;               // [j=192][c=64] : 12288
    float* ys = sm + 12288;       // [c=64][t=64]  :  4096
    const int tid  = threadIdx.x;
    const int brb  = blockIdx.y;
    const int tile = blockIdx.x;
    const int n0   = tile * 64;

    const float* yp = g_y + (size_t)brb * CPB * NPIX;
    for (int idx = tid; idx < 12288; idx += 256) wq[idx] = wqkv[idx];
    for (int idx = tid; idx < 4096;  idx += 256) {
        int c = idx >> 6, t = idx & 63;
        ys[idx] = yp[(size_t)c*NPIX + n0 + t];
    }
    __syncthreads();

    const int tok = (tid & 15) * 4;
    const int j0  = (tid >> 4) * 12;
    float acc[12][4];
    #pragma unroll
    for (int jj = 0; jj < 12; jj++) { acc[jj][0]=acc[jj][1]=acc[jj][2]=acc[jj][3]=0.f; }

    #pragma unroll 2
    for (int c4 = 0; c4 < 64; c4 += 4) {
        float4 ya0 = *(const float4*)&ys[(c4    )*64 + tok];
        float4 ya1 = *(const float4*)&ys[(c4 + 1)*64 + tok];
        float4 ya2 = *(const float4*)&ys[(c4 + 2)*64 + tok];
        float4 ya3 = *(const float4*)&ys[(c4 + 3)*64 + tok];
        #pragma unroll
        for (int jj = 0; jj < 12; jj++) {
            float4 w4 = *(const float4*)&wq[(j0 + jj)*64 + c4];
            acc[jj][0] += ya0.x*w4.x + ya1.x*w4.y + ya2.x*w4.z + ya3.x*w4.w;
            acc[jj][1] += ya0.y*w4.x + ya1.y*w4.y + ya2.y*w4.z + ya3.y*w4.w;
            acc[jj][2] += ya0.z*w4.x + ya1.z*w4.y + ya2.z*w4.z + ya3.z*w4.w;
            acc[jj][3] += ya0.w*w4.x + ya1.w*w4.y + ya2.w*w4.z + ya3.w*w4.w;
        }
    }
    __syncthreads();   // all reads of wq/ys done before overlay

    float* qkvs = sm;  // [t=64][j stride QSTR]
    #pragma unroll
    for (int jj = 0; jj < 12; jj++)
        #pragma unroll
        for (int i = 0; i < 4; i++)
            qkvs[(tok + i)*QSTR + j0 + jj] = acc[jj][i];
    __syncthreads();

    // k softmax over head-dim (8), normalized, written back in place
    for (int th = tid; th < 512; th += 256) {
        int t = th & 63, h = th >> 6;
        float* kr = &qkvs[t*QSTR + 64 + h*8];
        float kv[8];
        #pragma unroll
        for (int d = 0; d < 8; d++) kv[d] = kr[d];
        float m = kv[0];
        #pragma unroll
        for (int d = 1; d < 8; d++) m = fmaxf(m, kv[d]);
        float e[8]; float s = 0.f;
        #pragma unroll
        for (int d = 0; d < 8; d++) { e[d] = __expf(kv[d] - m); s += e[d]; }
        float inv = 1.f / s;
        #pragma unroll
        for (int d = 0; d < 8; d++) kr[d] = e[d] * inv;
    }
    __syncthreads();

    // -- per-tile q stats: rows hd=0..63, 4 threads/row over 64 tokens --
    {
        int hd = tid >> 2, part = tid & 3;
        float vals[16];
        #pragma unroll
        for (int i = 0; i < 16; i++) vals[i] = qkvs[(part*16 + i)*QSTR + hd];
        float m = vals[0];
        #pragma unroll
        for (int i = 1; i < 16; i++) m = fmaxf(m, vals[i]);
        m = fmaxf(m, __shfl_xor_sync(0xffffffffu, m, 1));
        m = fmaxf(m, __shfl_xor_sync(0xffffffffu, m, 2));
        float s = 0.f;
        #pragma unroll
        for (int i = 0; i < 16; i++) s += __expf(vals[i] - m);
        s += __shfl_xor_sync(0xffffffffu, s, 1);
        s += __shfl_xor_sync(0xffffffffu, s, 2);
        if (part == 0) {
            size_t r = (size_t)brb*64 + hd;
            g_pm[r*NTILES + tile] = m;
            g_ps[r*NTILES + tile] = s;
        }
    }

    // -- partial ctx: thread = (h, d, e-pair); sum over 64 tokens --
    {
        int h  = tid >> 5;
        int d  = (tid >> 2) & 7;
        int ep = tid & 3;
        float ce0 = 0.f, ce1 = 0.f;
        #pragma unroll 4
        for (int t = 0; t < 64; t++) {
            float  kv = qkvs[t*QSTR + 64 + h*8 + d];
            float2 vv = *(const float2*)&qkvs[t*QSTR + 128 + h*8 + 2*ep];
            ce0 += kv * vv.x;
            ce1 += kv * vv.y;
        }
        float2 r = make_float2(ce0, ce1);
        *(float2*)&g_cpart[((size_t)tile*64 + brb)*512 + h*64 + d*8 + 2*ep] = r;
    }

    // q scatter (raw) to [brb][hd][n]
    for (int idx = tid; idx < 4096; idx += 256) {
        int hd = idx >> 6, t = idx & 63;
        g_q[((size_t)brb*64 + hd)*NPIX + n0 + t] = qkvs[t*QSTR + hd];
    }
}

// ---------------- K3a: reduce partial ctx over tiles ------------------------
// grid 64 (brb), block 512
__global__ void ctx_reduce_kernel()
{
    const int brb = blockIdx.x;
    const int tid = threadIdx.x;
    float s = 0.f;
    const float* p = g_cpart + (size_t)brb*512 + tid;
    #pragma unroll 4
    for (int t = 0; t < NTILES; t++)
        s += p[(size_t)t*64*512];
    g_ctx[(size_t)brb*512 + tid] = s;
}

// ---------------- K3b: combine per-tile q stats ----------------------------
// grid 4096 rows, block 32
__global__ void qcombine_kernel()
{
    const int r    = blockIdx.x;
    const int lane = threadIdx.x;
    const float* pm = g_pm + (size_t)r*NTILES;
    const float* ps = g_ps + (size_t)r*NTILES;

    float mv[4]; float m = -1e30f;
    #pragma unroll
    for (int j = 0; j < 4; j++) {
        int t = lane + 32*j;
        mv[j] = (t < NTILES) ? pm[t] : -1e30f;
        m = fmaxf(m, mv[j]);
    }
    #pragma unroll
    for (int off = 16; off; off >>= 1)
        m = fmaxf(m, __shfl_xor_sync(0xffffffffu, m, off));

    float s = 0.f;
    #pragma unroll
    for (int j = 0; j < 4; j++) {
        int t = lane + 32*j;
        if (t < NTILES) s += ps[t] * __expf(mv[j] - m);
    }
    #pragma unroll
    for (int off = 16; off; off >>= 1)
        s += __shfl_xor_sync(0xffffffffu, s, off);

    if (lane == 0) { g_qm[r] = m; g_qs[r] = s; }
}

// ---------------- K5: out = softmax(q)@ctx, scrambled reshape, proj, scale --
// grid (200 group-tiles, 64 br*b), block 256
__global__ void attn_out_kernel(const float* __restrict__ wproj,
                                const float* __restrict__ bproj,
                                const float* __restrict__ scale)
{
    __shared__ float wp   [64*68];   // [f][o] padded
    __shared__ float out_s[32*64];   // [g][f]
    __shared__ float p_s  [32*64];   // [g][o]
    __shared__ float ctx_s[64];
    __shared__ float m_s[8];
    const int tid = threadIdx.x;
    const int brb = blockIdx.y;
    const int br  = brb >> 4;
    const int g0  = blockIdx.x * 32;       // n' base; one head per block
    const int h   = g0 / 800;

    for (int idx = tid; idx < 4096; idx += 256) {
        int o = idx >> 6, f = idx & 63;
        wp[f*68 + o] = wproj[idx];          // wproj[o][f]
    }
    if (tid < 64) {
        int d = tid >> 3;
        float invS = 1.f / g_qs[(size_t)brb*64 + h*8 + d];
        ctx_s[tid] = g_ctx[((size_t)brb*NHEADS + h)*64 + tid] * invS;
    }
    if (tid >= 64 && tid < 72) m_s[tid - 64] = g_qm[(size_t)brb*64 + h*8 + (tid - 64)];
    __syncthreads();

    // Phase A: out[g][i*8+e] = sum_d exp(q[h,d,n]-m_d) * ctx'[d,e]
    {
        int g = tid >> 3, i = tid & 7;
        int np = g0 + g;
        int n0 = (np % 800) * 8;
        const float* qp = g_q + ((size_t)brb*64 + h*8)*NPIX + n0 + i;
        float oo[8] = {0,0,0,0,0,0,0,0};
        #pragma unroll
        for (int d = 0; d < 8; d++) {
            float qv = __expf(qp[(size_t)d*NPIX] - m_s[d]);
            #pragma unroll
            for (int e = 0; e < 8; e++) oo[e] += qv * ctx_s[d*8 + e];
        }
        #pragma unroll
        for (int e = 0; e < 8; e++) out_s[g*64 + i*8 + e] = oo[e];
    }
    __syncthreads();

    // Phase B: p[g][o] = (sum_f out[g][f]*wproj[o][f] + bproj[o]) * scale[br]
    {
        int gp = tid >> 4;
        int o4 = (tid & 15) * 4;
        float p0[4] = {0,0,0,0}, p1[4] = {0,0,0,0};
        #pragma unroll 8
        for (int f = 0; f < 64; f++) {
            float a0 = out_s[(2*gp    )*64 + f];
            float a1 = out_s[(2*gp + 1)*64 + f];
            float4 w4 = *(const float4*)&wp[f*68 + o4];
            p0[0] += a0*w4.x; p0[1] += a0*w4.y; p0[2] += a0*w4.z; p0[3] += a0*w4.w;
            p1[0] += a1*w4.x; p1[1] += a1*w4.y; p1[2] += a1*w4.z; p1[3] += a1*w4.w;
        }
        float scl  = __ldg(&scale[br]);
        float4 bp4 = *(const float4*)&bproj[o4];
        float4 r0, r1;
        r0.x = (p0[0]+bp4.x)*scl; r0.y = (p0[1]+bp4.y)*scl;
        r0.z = (p0[2]+bp4.z)*scl; r0.w = (p0[3]+bp4.w)*scl;
        r1.x = (p1[0]+bp4.x)*scl; r1.y = (p1[1]+bp4.y)*scl;
        r1.z = (p1[2]+bp4.z)*scl; r1.w = (p1[3]+bp4.w)*scl;
        *(float4*)&p_s[(2*gp    )*64 + o4] = r0;
        *(float4*)&p_s[(2*gp + 1)*64 + o4] = r1;
    }
    __syncthreads();

    float* ap = g_att + (size_t)brb*64*NPIX;
    for (int idx = tid; idx < 64*8; idx += 256) {
        int o = idx >> 3, seg = idx & 7;
        float4 r;
        r.x = p_s[(seg*4 + 0)*64 + o];
        r.y = p_s[(seg*4 + 1)*64 + o];
        r.z = p_s[(seg*4 + 2)*64 + o];
        r.w = p_s[(seg*4 + 3)*64 + o];
        *(float4*)&ap[(size_t)o*NPIX + g0 + seg*4] = r;
    }
}

// ---------------- K6: final 256x256 GEMM over pixels (R1 plain FFMA) --------
// grid (100 n-tiles, 4 o-tiles, 16 b), block 256
__global__ void final_kernel(const float* __restrict__ wf,
                             const float* __restrict__ bf,
                             float* __restrict__ out)
{
    __shared__ float a_s[32*68];   // [k][o] padded
    __shared__ float b_s[32*64];   // [k][n]
    const int tid = threadIdx.x;
    const int n0  = blockIdx.x * 64;
    const int o0  = blockIdx.y * 64;
    const int b   = blockIdx.z;

    const int n4 = (tid & 15) * 4, o4 = (tid >> 4) * 4;
    float acc[4][4];
    #pragma unroll
    for (int i = 0; i < 4; i++)
        #pragma unroll
        for (int j = 0; j < 4; j++) acc[i][j] = 0.f;

    for (int kc = 0; kc < 256; kc += 32) {
        for (int idx = tid; idx < 32*64; idx += 256) {
            int o = idx >> 5, k = idx & 31;
            a_s[k*68 + o] = wf[(size_t)(o0 + o)*256 + kc + k];
        }
        for (int idx = tid; idx < 32*64; idx += 256) {
            int k = idx >> 6, n = idx & 63;
            int kk = kc + k;
            b_s[k*64 + n] =
                g_att[(((size_t)(kk >> 6)*NB + b)*64 + (kk & 63))*NPIX + n0 + n];
        }
        __syncthreads();
        #pragma unroll
        for (int k = 0; k < 32; k++) {
            float4 a4 = *(const float4*)&a_s[k*68 + o4];
            float4 b4 = *(const float4*)&b_s[k*64 + n4];
            float av[4] = {a4.x, a4.y, a4.z, a4.w};
            float bv[4] = {b4.x, b4.y, b4.z, b4.w};
            #pragma unroll
            for (int i = 0; i < 4; i++)
                #pragma unroll
                for (int j = 0; j < 4; j++) acc[i][j] += av[i] * bv[j];
        }
        __syncthreads();
    }
    float4 bf4 = *(const float4*)&bf[o0 + o4];
    float bb[4] = {bf4.x, bf4.y, bf4.z, bf4.w};
    #pragma unroll
    for (int i = 0; i < 4; i++) {
        float4 r = make_float4(acc[i][0] + bb[i], acc[i][1] + bb[i],
                               acc[i][2] + bb[i], acc[i][3] + bb[i]);
        *(float4*)&out[((size_t)b*256 + o0 + o4 + i)*NPIX + n0 + n4] = r;
    }
}

// ---------------- launch ------------------------------------------------------
extern "C" void kernel_launch(void* const* d_in, const int* in_sizes, int n_in,
                              void* d_out, int out_size)
{
    const float* x     = (const float*)d_in[0];
    const float* w3    = (const float*)d_in[1];
    const float* b3    = (const float*)d_in[2];
    const float* w5    = (const float*)d_in[3];
    const float* b5    = (const float*)d_in[4];
    const float* w7    = (const float*)d_in[5];
    const float* b7    = (const float*)d_in[6];
    const float* w9    = (const float*)d_in[7];
    const float* b9    = (const float*)d_in[8];
    const float* wqkv  = (const float*)d_in[9];
    const float* wproj = (const float*)d_in[10];
    const float* bproj = (const float*)d_in[11];
    const float* wf    = (const float*)d_in[12];
    const float* bf    = (const float*)d_in[13];
    const float* scale = (const float*)d_in[14];
    float* out = (float*)d_out;

    dim3 gconv(5, 64, 16);
    dwconv_kernel<3><<<gconv, 320>>>(x, w3, b3, 0);
    dwconv_kernel<5><<<gconv, 320>>>(x, w5, b5, 1);
    dwconv_kernel<7><<<gconv, 320>>>(x, w7, b7, 2);
    dwconv_kernel<9><<<gconv, 320>>>(x, w9, b9, 3);

    static bool attr_set = false;
    if (!attr_set) {
        cudaFuncSetAttribute(qkv_kernel,
                             cudaFuncAttributeMaxDynamicSharedMemorySize, 65536);
        attr_set = true;
    }
    qkv_kernel<<<dim3(100, 64), 256, 65536>>>(wqkv);
    ctx_reduce_kernel<<<64, 512>>>();
    qcombine_kernel<<<4096, 32>>>();
    attn_out_kernel<<<dim3(200, 64), 256>>>(wproj, bproj, scale);
    final_kernel<<<dim3(100, 4, 16), 256>>>(wf, bf, out);
}

// round 5
// speedup vs baseline: 1.3354x; 1.2089x over previous
#include <cuda_runtime.h>
#include <cstdint>

#define BRANCHES 4
#define NB 16
#define CPB 64
#define HGT 80
#define WID 80
#define NPIX 6400
#define NHEADS 8
#define NTILES 100

// ---------------- scratch ----------------------------------------------------
__device__ float g_y    [(size_t)BRANCHES*NB*CPB*NPIX];   // dwconv out [brb][c][n]
__device__ float g_q    [(size_t)BRANCHES*NB*CPB*NPIX];   // raw q [brb][h*8+d][n]
__device__ float g_ctx  [(size_t)BRANCHES*NB*NHEADS*64];  // ctx [brb][h][d*8+e]
__device__ float g_cpart[(size_t)NTILES*64*512];          // partial ctx [tile][brb][cell]
__device__ float g_pm   [(size_t)4096*NTILES];            // per-tile q max [row][tile]
__device__ float g_ps   [(size_t)4096*NTILES];            // per-tile q sumexp [row][tile]
__device__ float g_qm   [(size_t)4096];                   // global q max per row
__device__ float g_qs   [(size_t)4096];                   // global q sumexp per row
__device__ float g_att  [(size_t)BRANCHES*NB*CPB*NPIX];   // attention out [brb][o][n']

// ---------------- tf32 helpers ----------------------------------------------
__device__ __forceinline__ uint32_t f2tf32(float x) {
    uint32_t r;
    asm("cvt.rna.tf32.f32 %0, %1;" : "=r"(r) : "f"(x));
    return r;
}
__device__ __forceinline__ void mma_tf32(float d[4],
                                         uint32_t a0, uint32_t a1, uint32_t a2, uint32_t a3,
                                         uint32_t b0, uint32_t b1) {
    asm volatile(
        "mma.sync.aligned.m16n8k8.row.col.f32.tf32.tf32.f32 "
        "{%0,%1,%2,%3}, {%4,%5,%6,%7}, {%8,%9}, {%0,%1,%2,%3};"
        : "+f"(d[0]), "+f"(d[1]), "+f"(d[2]), "+f"(d[3])
        : "r"(a0), "r"(a1), "r"(a2), "r"(a3), "r"(b0), "r"(b1));
}

// ---------------- K1: depthwise conv + bias + residual + relu ---------------
// grid (5 row-tiles, 64 channels, 16 batch), block 320 = 20x16
template<int KS>
__global__ void dwconv_kernel(const float* __restrict__ x,
                              const float* __restrict__ w,
                              const float* __restrict__ bias,
                              int br)
{
    __shared__ float tile[24*88];
    __shared__ float wsm[KS*KS];
    const int b    = blockIdx.z;
    const int c    = blockIdx.y;
    const int row0 = blockIdx.x * 16;
    const int tid  = threadIdx.x;

    if (tid < KS*KS) wsm[tid] = w[c*KS*KS + tid];
    const float bv = bias[c];
    const float* xp = x + ((size_t)b*256 + (size_t)br*64 + c) * NPIX;

    for (int idx = tid; idx < 24*88; idx += 320) {
        int r  = idx / 88, cl = idx % 88;
        int gh = row0 - 4 + r, gw = cl - 4;
        float v = 0.f;
        if (gh >= 0 && gh < HGT && gw >= 0 && gw < WID) v = xp[gh*WID + gw];
        tile[idx] = v;
    }
    __syncthreads();

    const int tx = tid % 20, ty = tid / 20;
    const int col0 = tx * 4;
    constexpr int PAD = KS / 2;
    float a0 = 0.f, a1 = 0.f, a2 = 0.f, a3 = 0.f;
    float win[KS + 3];
    #pragma unroll
    for (int kh = 0; kh < KS; kh++) {
        int base = (ty + 4 - PAD + kh)*88 + col0 + 4 - PAD;
        #pragma unroll
        for (int ww = 0; ww < KS + 3; ww++) win[ww] = tile[base + ww];
        #pragma unroll
        for (int kw = 0; kw < KS; kw++) {
            float wv = wsm[kh*KS + kw];
            a0 += win[kw    ] * wv;
            a1 += win[kw + 1] * wv;
            a2 += win[kw + 2] * wv;
            a3 += win[kw + 3] * wv;
        }
    }
    int cb = (ty + 4)*88 + col0 + 4;
    float* yp = g_y + (((size_t)br*NB + b)*CPB + c)*NPIX + (row0 + ty)*WID + col0;
    yp[0] = fmaxf(a0 + bv + tile[cb + 0], 0.f);
    yp[1] = fmaxf(a1 + bv + tile[cb + 1], 0.f);
    yp[2] = fmaxf(a2 + bv + tile[cb + 2], 0.f);
    yp[3] = fmaxf(a3 + bv + tile[cb + 3], 0.f);
}

// ---------------- K2: qkv GEMM + k-softmax + partial ctx + partial q stats --
// grid (100 token tiles, 64 br*b), block 256, dyn smem 65536B
#define QSTR 194
__global__ void qkv_kernel(const float* __restrict__ wqkv)
{
    extern __shared__ float sm[];
    float* wq = sm;               // [j=192][c=64] : 12288
    float* ys = sm + 12288;       // [c=64][t=64]  :  4096
    const int tid  = threadIdx.x;
    const int brb  = blockIdx.y;
    const int tile = blockIdx.x;
    const int n0   = tile * 64;

    const float* yp = g_y + (size_t)brb * CPB * NPIX;
    for (int idx = tid; idx < 12288; idx += 256) wq[idx] = wqkv[idx];
    for (int idx = tid; idx < 4096;  idx += 256) {
        int c = idx >> 6, t = idx & 63;
        ys[idx] = yp[(size_t)c*NPIX + n0 + t];
    }
    __syncthreads();

    const int tok = (tid & 15) * 4;
    const int j0  = (tid >> 4) * 12;
    float acc[12][4];
    #pragma unroll
    for (int jj = 0; jj < 12; jj++) { acc[jj][0]=acc[jj][1]=acc[jj][2]=acc[jj][3]=0.f; }

    #pragma unroll 2
    for (int c4 = 0; c4 < 64; c4 += 4) {
        float4 ya0 = *(const float4*)&ys[(c4    )*64 + tok];
        float4 ya1 = *(const float4*)&ys[(c4 + 1)*64 + tok];
        float4 ya2 = *(const float4*)&ys[(c4 + 2)*64 + tok];
        float4 ya3 = *(const float4*)&ys[(c4 + 3)*64 + tok];
        #pragma unroll
        for (int jj = 0; jj < 12; jj++) {
            float4 w4 = *(const float4*)&wq[(j0 + jj)*64 + c4];
            acc[jj][0] += ya0.x*w4.x + ya1.x*w4.y + ya2.x*w4.z + ya3.x*w4.w;
            acc[jj][1] += ya0.y*w4.x + ya1.y*w4.y + ya2.y*w4.z + ya3.y*w4.w;
            acc[jj][2] += ya0.z*w4.x + ya1.z*w4.y + ya2.z*w4.z + ya3.z*w4.w;
            acc[jj][3] += ya0.w*w4.x + ya1.w*w4.y + ya2.w*w4.z + ya3.w*w4.w;
        }
    }
    __syncthreads();

    float* qkvs = sm;  // [t=64][j stride QSTR]
    #pragma unroll
    for (int jj = 0; jj < 12; jj++)
        #pragma unroll
        for (int i = 0; i < 4; i++)
            qkvs[(tok + i)*QSTR + j0 + jj] = acc[jj][i];
    __syncthreads();

    // k softmax over head-dim (8), normalized, in place
    for (int th = tid; th < 512; th += 256) {
        int t = th & 63, h = th >> 6;
        float* kr = &qkvs[t*QSTR + 64 + h*8];
        float kv[8];
        #pragma unroll
        for (int d = 0; d < 8; d++) kv[d] = kr[d];
        float m = kv[0];
        #pragma unroll
        for (int d = 1; d < 8; d++) m = fmaxf(m, kv[d]);
        float e[8]; float s = 0.f;
        #pragma unroll
        for (int d = 0; d < 8; d++) { e[d] = __expf(kv[d] - m); s += e[d]; }
        float inv = 1.f / s;
        #pragma unroll
        for (int d = 0; d < 8; d++) kr[d] = e[d] * inv;
    }
    __syncthreads();

    // per-tile q stats
    {
        int hd = tid >> 2, part = tid & 3;
        float vals[16];
        #pragma unroll
        for (int i = 0; i < 16; i++) vals[i] = qkvs[(part*16 + i)*QSTR + hd];
        float m = vals[0];
        #pragma unroll
        for (int i = 1; i < 16; i++) m = fmaxf(m, vals[i]);
        m = fmaxf(m, __shfl_xor_sync(0xffffffffu, m, 1));
        m = fmaxf(m, __shfl_xor_sync(0xffffffffu, m, 2));
        float s = 0.f;
        #pragma unroll
        for (int i = 0; i < 16; i++) s += __expf(vals[i] - m);
        s += __shfl_xor_sync(0xffffffffu, s, 1);
        s += __shfl_xor_sync(0xffffffffu, s, 2);
        if (part == 0) {
            size_t r = (size_t)brb*64 + hd;
            g_pm[r*NTILES + tile] = m;
            g_ps[r*NTILES + tile] = s;
        }
    }

    // partial ctx
    {
        int h  = tid >> 5;
        int d  = (tid >> 2) & 7;
        int ep = tid & 3;
        float ce0 = 0.f, ce1 = 0.f;
        #pragma unroll 4
        for (int t = 0; t < 64; t++) {
            float  kv = qkvs[t*QSTR + 64 + h*8 + d];
            float2 vv = *(const float2*)&qkvs[t*QSTR + 128 + h*8 + 2*ep];
            ce0 += kv * vv.x;
            ce1 += kv * vv.y;
        }
        float2 r = make_float2(ce0, ce1);
        *(float2*)&g_cpart[((size_t)tile*64 + brb)*512 + h*64 + d*8 + 2*ep] = r;
    }

    // q scatter
    for (int idx = tid; idx < 4096; idx += 256) {
        int hd = idx >> 6, t = idx & 63;
        g_q[((size_t)brb*64 + hd)*NPIX + n0 + t] = qkvs[t*QSTR + hd];
    }
}

// ---------------- K3a: reduce partial ctx over tiles ------------------------
__global__ void ctx_reduce_kernel()
{
    const int brb = blockIdx.x;
    const int tid = threadIdx.x;
    float s = 0.f;
    const float* p = g_cpart + (size_t)brb*512 + tid;
    #pragma unroll 4
    for (int t = 0; t < NTILES; t++)
        s += p[(size_t)t*64*512];
    g_ctx[(size_t)brb*512 + tid] = s;
}

// ---------------- K3b: combine per-tile q stats ----------------------------
__global__ void qcombine_kernel()
{
    const int r    = blockIdx.x;
    const int lane = threadIdx.x;
    const float* pm = g_pm + (size_t)r*NTILES;
    const float* ps = g_ps + (size_t)r*NTILES;

    float mv[4]; float m = -1e30f;
    #pragma unroll
    for (int j = 0; j < 4; j++) {
        int t = lane + 32*j;
        mv[j] = (t < NTILES) ? pm[t] : -1e30f;
        m = fmaxf(m, mv[j]);
    }
    #pragma unroll
    for (int off = 16; off; off >>= 1)
        m = fmaxf(m, __shfl_xor_sync(0xffffffffu, m, off));

    float s = 0.f;
    #pragma unroll
    for (int j = 0; j < 4; j++) {
        int t = lane + 32*j;
        if (t < NTILES) s += ps[t] * __expf(mv[j] - m);
    }
    #pragma unroll
    for (int off = 16; off; off >>= 1)
        s += __shfl_xor_sync(0xffffffffu, s, off);

    if (lane == 0) { g_qm[r] = m; g_qs[r] = s; }
}

// ---------------- K5: out = softmax(q)@ctx, scrambled reshape, proj, scale --
// grid (200 group-tiles, 64 br*b), block 256
__global__ void attn_out_kernel(const float* __restrict__ wproj,
                                const float* __restrict__ bproj,
                                const float* __restrict__ scale)
{
    __shared__ float wp   [64*68];
    __shared__ float out_s[32*64];
    __shared__ float p_s  [32*64];
    __shared__ float ctx_s[64];
    __shared__ float m_s[8];
    const int tid = threadIdx.x;
    const int brb = blockIdx.y;
    const int br  = brb >> 4;
    const int g0  = blockIdx.x * 32;
    const int h   = g0 / 800;

    for (int idx = tid; idx < 4096; idx += 256) {
        int o = idx >> 6, f = idx & 63;
        wp[f*68 + o] = wproj[idx];
    }
    if (tid < 64) {
        int d = tid >> 3;
        float invS = 1.f / g_qs[(size_t)brb*64 + h*8 + d];
        ctx_s[tid] = g_ctx[((size_t)brb*NHEADS + h)*64 + tid] * invS;
    }
    if (tid >= 64 && tid < 72) m_s[tid - 64] = g_qm[(size_t)brb*64 + h*8 + (tid - 64)];
    __syncthreads();

    {
        int g = tid >> 3, i = tid & 7;
        int np = g0 + g;
        int n0 = (np % 800) * 8;
        const float* qp = g_q + ((size_t)brb*64 + h*8)*NPIX + n0 + i;
        float oo[8] = {0,0,0,0,0,0,0,0};
        #pragma unroll
        for (int d = 0; d < 8; d++) {
            float qv = __expf(qp[(size_t)d*NPIX] - m_s[d]);
            #pragma unroll
            for (int e = 0; e < 8; e++) oo[e] += qv * ctx_s[d*8 + e];
        }
        #pragma unroll
        for (int e = 0; e < 8; e++) out_s[g*64 + i*8 + e] = oo[e];
    }
    __syncthreads();

    {
        int gp = tid >> 4;
        int o4 = (tid & 15) * 4;
        float p0[4] = {0,0,0,0}, p1[4] = {0,0,0,0};
        #pragma unroll 8
        for (int f = 0; f < 64; f++) {
            float a0 = out_s[(2*gp    )*64 + f];
            float a1 = out_s[(2*gp + 1)*64 + f];
            float4 w4 = *(const float4*)&wp[f*68 + o4];
            p0[0] += a0*w4.x; p0[1] += a0*w4.y; p0[2] += a0*w4.z; p0[3] += a0*w4.w;
            p1[0] += a1*w4.x; p1[1] += a1*w4.y; p1[2] += a1*w4.z; p1[3] += a1*w4.w;
        }
        float scl  = __ldg(&scale[br]);
        float4 bp4 = *(const float4*)&bproj[o4];
        float4 r0, r1;
        r0.x = (p0[0]+bp4.x)*scl; r0.y = (p0[1]+bp4.y)*scl;
        r0.z = (p0[2]+bp4.z)*scl; r0.w = (p0[3]+bp4.w)*scl;
        r1.x = (p1[0]+bp4.x)*scl; r1.y = (p1[1]+bp4.y)*scl;
        r1.z = (p1[2]+bp4.z)*scl; r1.w = (p1[3]+bp4.w)*scl;
        *(float4*)&p_s[(2*gp    )*64 + o4] = r0;
        *(float4*)&p_s[(2*gp + 1)*64 + o4] = r1;
    }
    __syncthreads();

    float* ap = g_att + (size_t)brb*64*NPIX;
    for (int idx = tid; idx < 64*8; idx += 256) {
        int o = idx >> 3, seg = idx & 7;
        float4 r;
        r.x = p_s[(seg*4 + 0)*64 + o];
        r.y = p_s[(seg*4 + 1)*64 + o];
        r.z = p_s[(seg*4 + 2)*64 + o];
        r.w = p_s[(seg*4 + 3)*64 + o];
        *(float4*)&ap[(size_t)o*NPIX + g0 + seg*4] = r;
    }
}

// ---------------- K6: final 256x256 GEMM via mma.sync tf32 ------------------
// grid (100 n-tiles, 16 b), block 256 = 8 warps (4 o x 2 n)
// block tile: 256 o x 64 n, k chunked by 32
#define ASTR 36   // A smem stride (floats per o row)
#define BSTR 72   // B smem stride (floats per k row)
__global__ void final_kernel(const float* __restrict__ wf,
                             const float* __restrict__ bf,
                             float* __restrict__ out)
{
    __shared__ uint32_t As[256*ASTR];   // [o][k] tf32 bits
    __shared__ uint32_t Bs[32*BSTR];    // [k][n] tf32 bits
    const int tid = threadIdx.x;
    const int n0  = blockIdx.x * 64;
    const int b   = blockIdx.y;

    const int warp = tid >> 5, lane = tid & 31;
    const int wo = (warp >> 1) * 64;     // warp o base within 256
    const int wn = (warp & 1) * 32;      // warp n base within 64
    const int g = lane >> 2, t = lane & 3;

    float d[4][4][4];
    #pragma unroll
    for (int mf = 0; mf < 4; mf++)
        #pragma unroll
        for (int nf = 0; nf < 4; nf++)
            #pragma unroll
            for (int r = 0; r < 4; r++) d[mf][nf][r] = 0.f;

    for (int kc = 0; kc < 256; kc += 32) {
        // stage A: wf[o][kc+k] -> As[o][k], 8192 elements
        #pragma unroll
        for (int it = 0; it < 32; it++) {
            int idx = tid + it*256;
            int o = idx >> 5, k = idx & 31;
            As[o*ASTR + k] = f2tf32(wf[(size_t)o*256 + kc + k]);
        }
        // stage B: g_att[kk-mapped][n0+n] -> Bs[k][n], 2048 elements
        #pragma unroll
        for (int it = 0; it < 8; it++) {
            int idx = tid + it*256;
            int k = idx >> 6, n = idx & 63;
            int kk = kc + k;
            Bs[k*BSTR + n] = f2tf32(
                g_att[(((size_t)(kk >> 6)*NB + b)*64 + (kk & 63))*NPIX + n0 + n]);
        }
        __syncthreads();

        #pragma unroll
        for (int kf = 0; kf < 4; kf++) {
            int k0 = kf*8;
            uint32_t a[4][4];
            #pragma unroll
            for (int mf = 0; mf < 4; mf++) {
                int orow = wo + mf*16 + g;
                a[mf][0] = As[(orow    )*ASTR + k0 + t];
                a[mf][1] = As[(orow + 8)*ASTR + k0 + t];
                a[mf][2] = As[(orow    )*ASTR + k0 + t + 4];
                a[mf][3] = As[(orow + 8)*ASTR + k0 + t + 4];
            }
            uint32_t bb[4][2];
            #pragma unroll
            for (int nf = 0; nf < 4; nf++) {
                int ncol = wn + nf*8 + g;
                bb[nf][0] = Bs[(k0 + t    )*BSTR + ncol];
                bb[nf][1] = Bs[(k0 + t + 4)*BSTR + ncol];
            }
            #pragma unroll
            for (int mf = 0; mf < 4; mf++)
                #pragma unroll
                for (int nf = 0; nf < 4; nf++)
                    mma_tf32(d[mf][nf], a[mf][0], a[mf][1], a[mf][2], a[mf][3],
                             bb[nf][0], bb[nf][1]);
        }
        __syncthreads();
    }

    // epilogue: D[m][n] + bf[o]
    #pragma unroll
    for (int mf = 0; mf < 4; mf++) {
        int o_lo = wo + mf*16 + g;
        int o_hi = o_lo + 8;
        float bf_lo = __ldg(&bf[o_lo]);
        float bf_hi = __ldg(&bf[o_hi]);
        float* base_lo = &out[((size_t)b*256 + o_lo)*NPIX + n0 + wn];
        float* base_hi = &out[((size_t)b*256 + o_hi)*NPIX + n0 + wn];
        #pragma unroll
        for (int nf = 0; nf < 4; nf++) {
            int nc = nf*8 + 2*t;
            float2 r0 = make_float2(d[mf][nf][0] + bf_lo, d[mf][nf][1] + bf_lo);
            float2 r1 = make_float2(d[mf][nf][2] + bf_hi, d[mf][nf][3] + bf_hi);
            *(float2*)&base_lo[nc] = r0;
            *(float2*)&base_hi[nc] = r1;
        }
    }
}

// ---------------- launch ------------------------------------------------------
extern "C" void kernel_launch(void* const* d_in, const int* in_sizes, int n_in,
                              void* d_out, int out_size)
{
    const float* x     = (const float*)d_in[0];
    const float* w3    = (const float*)d_in[1];
    const float* b3    = (const float*)d_in[2];
    const float* w5    = (const float*)d_in[3];
    const float* b5    = (const float*)d_in[4];
    const float* w7    = (const float*)d_in[5];
    const float* b7    = (const float*)d_in[6];
    const float* w9    = (const float*)d_in[7];
    const float* b9    = (const float*)d_in[8];
    const float* wqkv  = (const float*)d_in[9];
    const float* wproj = (const float*)d_in[10];
    const float* bproj = (const float*)d_in[11];
    const float* wf    = (const float*)d_in[12];
    const float* bf    = (const float*)d_in[13];
    const float* scale = (const float*)d_in[14];
    float* out = (float*)d_out;

    dim3 gconv(5, 64, 16);
    dwconv_kernel<3><<<gconv, 320>>>(x, w3, b3, 0);
    dwconv_kernel<5><<<gconv, 320>>>(x, w5, b5, 1);
    dwconv_kernel<7><<<gconv, 320>>>(x, w7, b7, 2);
    dwconv_kernel<9><<<gconv, 320>>>(x, w9, b9, 3);

    static bool attr_set = false;
    if (!attr_set) {
        cudaFuncSetAttribute(qkv_kernel,
                             cudaFuncAttributeMaxDynamicSharedMemorySize, 65536);
        attr_set = true;
    }
    qkv_kernel<<<dim3(100, 64), 256, 65536>>>(wqkv);
    ctx_reduce_kernel<<<64, 512>>>();
    qcombine_kernel<<<4096, 32>>>();
    attn_out_kernel<<<dim3(200, 64), 256>>>(wproj, bproj, scale);
    final_kernel<<<dim3(100, 16), 256>>>(wf, bf, out);
}

// round 6
// speedup vs baseline: 1.6456x; 1.2323x over previous
#include <cuda_runtime.h>
#include <cstdint>

#define BRANCHES 4
#define NB 16
#define CPB 64
#define HGT 80
#define WID 80
#define NPIX 6400
#define NHEADS 8
#define NTILES 100

// ---------------- scratch ----------------------------------------------------
__device__ float g_y    [(size_t)BRANCHES*NB*CPB*NPIX];   // dwconv out [brb][c][n]
__device__ float g_q    [(size_t)BRANCHES*NB*CPB*NPIX];   // raw q [brb][h*8+d][n]
__device__ float g_ctx  [(size_t)BRANCHES*NB*NHEADS*64];  // ctx [brb][h][d*8+e]
__device__ float g_cpart[(size_t)NTILES*64*512];          // partial ctx [tile][brb][cell]
__device__ float g_pm   [(size_t)4096*NTILES];            // per-tile q max [row][tile]
__device__ float g_ps   [(size_t)4096*NTILES];            // per-tile q sumexp [row][tile]
__device__ float g_qm   [(size_t)4096];                   // global q max per row
__device__ float g_qs   [(size_t)4096];                   // global q sumexp per row
__device__ float g_att  [(size_t)BRANCHES*NB*CPB*NPIX];   // attention out [brb][o][n']

// ---------------- tf32 helpers ----------------------------------------------
__device__ __forceinline__ uint32_t f2tf32(float x) {
    uint32_t r;
    asm("cvt.rna.tf32.f32 %0, %1;" : "=r"(r) : "f"(x));
    return r;
}
__device__ __forceinline__ void mma_tf32(float d[4],
                                         uint32_t a0, uint32_t a1, uint32_t a2, uint32_t a3,
                                         uint32_t b0, uint32_t b1) {
    asm volatile(
        "mma.sync.aligned.m16n8k8.row.col.f32.tf32.tf32.f32 "
        "{%0,%1,%2,%3}, {%4,%5,%6,%7}, {%8,%9}, {%0,%1,%2,%3};"
        : "+f"(d[0]), "+f"(d[1]), "+f"(d[2]), "+f"(d[3])
        : "r"(a0), "r"(a1), "r"(a2), "r"(a3), "r"(b0), "r"(b1));
}
// split x into hi (tf32 bits) and lo (tf32 bits of residual)
__device__ __forceinline__ void tf32_split(float x, uint32_t& hi, uint32_t& lo) {
    hi = f2tf32(x);
    lo = f2tf32(x - __uint_as_float(hi));
}

// ---------------- K1: depthwise conv + bias + residual + relu ---------------
template<int KS>
__global__ void dwconv_kernel(const float* __restrict__ x,
                              const float* __restrict__ w,
                              const float* __restrict__ bias,
                              int br)
{
    __shared__ float tile[24*88];
    __shared__ float wsm[KS*KS];
    const int b    = blockIdx.z;
    const int c    = blockIdx.y;
    const int row0 = blockIdx.x * 16;
    const int tid  = threadIdx.x;

    if (tid < KS*KS) wsm[tid] = w[c*KS*KS + tid];
    const float bv = bias[c];
    const float* xp = x + ((size_t)b*256 + (size_t)br*64 + c) * NPIX;

    for (int idx = tid; idx < 24*88; idx += 320) {
        int r  = idx / 88, cl = idx % 88;
        int gh = row0 - 4 + r, gw = cl - 4;
        float v = 0.f;
        if (gh >= 0 && gh < HGT && gw >= 0 && gw < WID) v = xp[gh*WID + gw];
        tile[idx] = v;
    }
    __syncthreads();

    const int tx = tid % 20, ty = tid / 20;
    const int col0 = tx * 4;
    constexpr int PAD = KS / 2;
    float a0 = 0.f, a1 = 0.f, a2 = 0.f, a3 = 0.f;
    float win[KS + 3];
    #pragma unroll
    for (int kh = 0; kh < KS; kh++) {
        int base = (ty + 4 - PAD + kh)*88 + col0 + 4 - PAD;
        #pragma unroll
        for (int ww = 0; ww < KS + 3; ww++) win[ww] = tile[base + ww];
        #pragma unroll
        for (int kw = 0; kw < KS; kw++) {
            float wv = wsm[kh*KS + kw];
            a0 += win[kw    ] * wv;
            a1 += win[kw + 1] * wv;
            a2 += win[kw + 2] * wv;
            a3 += win[kw + 3] * wv;
        }
    }
    int cb = (ty + 4)*88 + col0 + 4;
    float* yp = g_y + (((size_t)br*NB + b)*CPB + c)*NPIX + (row0 + ty)*WID + col0;
    yp[0] = fmaxf(a0 + bv + tile[cb + 0], 0.f);
    yp[1] = fmaxf(a1 + bv + tile[cb + 1], 0.f);
    yp[2] = fmaxf(a2 + bv + tile[cb + 2], 0.f);
    yp[3] = fmaxf(a3 + bv + tile[cb + 3], 0.f);
}

// ---------------- K2: qkv via 3xTF32 MMA + k-softmax + partial ctx/stats ----
// grid (100 token tiles, 64 br*b), block 256 = 8 warps (2 m x 4 n)
// smem: wq fp32 [192][68] @0 (13056 f), ys fp32 [64][72] @13056 (4608 f)
// overlay after MMA: qkvs [t=64][stride 194] @0
#define QSTR 194
#define WQS  68
#define YSS  72
__global__ void qkv_kernel(const float* __restrict__ wqkv)
{
    extern __shared__ float sm[];
    float* wq = sm;                 // [j][c] stride WQS
    float* ys = sm + 13056;         // [c][t] stride YSS
    const int tid  = threadIdx.x;
    const int brb  = blockIdx.y;
    const int tile = blockIdx.x;
    const int n0   = tile * 64;

    const float* yp = g_y + (size_t)brb * CPB * NPIX;
    for (int idx = tid; idx < 12288; idx += 256) {
        int j = idx >> 6, c = idx & 63;
        wq[j*WQS + c] = wqkv[idx];
    }
    for (int idx = tid; idx < 4096; idx += 256) {
        int c = idx >> 6, t = idx & 63;
        ys[c*YSS + t] = yp[(size_t)c*NPIX + n0 + t];
    }
    __syncthreads();

    // MMA: warp grid 2(m) x 4(n); each warp: 6 m16-tiles x 2 n8-tiles, k=64
    const int warp = tid >> 5, lane = tid & 31;
    const int wm = (warp >> 2) * 96;      // 0 or 96
    const int wn = (warp & 3) * 16;       // 0,16,32,48
    const int g = lane >> 2, t = lane & 3;

    float d[6][2][4];
    #pragma unroll
    for (int mf = 0; mf < 6; mf++)
        #pragma unroll
        for (int nf = 0; nf < 2; nf++)
            #pragma unroll
            for (int r = 0; r < 4; r++) d[mf][nf][r] = 0.f;

    #pragma unroll
    for (int ks = 0; ks < 8; ks++) {
        const int k0 = ks * 8;
        // B fragments (hi/lo) for 2 n-tiles
        uint32_t bh[2][2], bl[2][2];
        #pragma unroll
        for (int nf = 0; nf < 2; nf++) {
            int ncol = wn + nf*8 + g;
            float f0 = ys[(k0 + t    )*YSS + ncol];
            float f1 = ys[(k0 + t + 4)*YSS + ncol];
            tf32_split(f0, bh[nf][0], bl[nf][0]);
            tf32_split(f1, bh[nf][1], bl[nf][1]);
        }
        #pragma unroll
        for (int mf = 0; mf < 6; mf++) {
            int r0 = wm + mf*16 + g;
            float fa0 = wq[(r0    )*WQS + k0 + t];
            float fa1 = wq[(r0 + 8)*WQS + k0 + t];
            float fa2 = wq[(r0    )*WQS + k0 + t + 4];
            float fa3 = wq[(r0 + 8)*WQS + k0 + t + 4];
            uint32_t ah[4], al[4];
            tf32_split(fa0, ah[0], al[0]);
            tf32_split(fa1, ah[1], al[1]);
            tf32_split(fa2, ah[2], al[2]);
            tf32_split(fa3, ah[3], al[3]);
            #pragma unroll
            for (int nf = 0; nf < 2; nf++) {
                mma_tf32(d[mf][nf], ah[0], ah[1], ah[2], ah[3], bl[nf][0], bl[nf][1]);
                mma_tf32(d[mf][nf], al[0], al[1], al[2], al[3], bh[nf][0], bh[nf][1]);
                mma_tf32(d[mf][nf], ah[0], ah[1], ah[2], ah[3], bh[nf][0], bh[nf][1]);
            }
        }
    }
    __syncthreads();   // done reading wq/ys

    // overlay: qkvs [t][j] stride QSTR
    float* qkvs = sm;
    #pragma unroll
    for (int mf = 0; mf < 6; mf++) {
        int r0 = wm + mf*16 + g;
        #pragma unroll
        for (int nf = 0; nf < 2; nf++) {
            int c0 = wn + nf*8 + 2*t;
            qkvs[(c0    )*QSTR + r0    ] = d[mf][nf][0];
            qkvs[(c0 + 1)*QSTR + r0    ] = d[mf][nf][1];
            qkvs[(c0    )*QSTR + r0 + 8] = d[mf][nf][2];
            qkvs[(c0 + 1)*QSTR + r0 + 8] = d[mf][nf][3];
        }
    }
    __syncthreads();

    // k softmax over head-dim (8), normalized, in place
    for (int th = tid; th < 512; th += 256) {
        int tt = th & 63, h = th >> 6;
        float* kr = &qkvs[tt*QSTR + 64 + h*8];
        float kv[8];
        #pragma unroll
        for (int dd = 0; dd < 8; dd++) kv[dd] = kr[dd];
        float m = kv[0];
        #pragma unroll
        for (int dd = 1; dd < 8; dd++) m = fmaxf(m, kv[dd]);
        float e[8]; float s = 0.f;
        #pragma unroll
        for (int dd = 0; dd < 8; dd++) { e[dd] = __expf(kv[dd] - m); s += e[dd]; }
        float inv = 1.f / s;
        #pragma unroll
        for (int dd = 0; dd < 8; dd++) kr[dd] = e[dd] * inv;
    }
    __syncthreads();

    // per-tile q stats
    {
        int hd = tid >> 2, part = tid & 3;
        float vals[16];
        #pragma unroll
        for (int i = 0; i < 16; i++) vals[i] = qkvs[(part*16 + i)*QSTR + hd];
        float m = vals[0];
        #pragma unroll
        for (int i = 1; i < 16; i++) m = fmaxf(m, vals[i]);
        m = fmaxf(m, __shfl_xor_sync(0xffffffffu, m, 1));
        m = fmaxf(m, __shfl_xor_sync(0xffffffffu, m, 2));
        float s = 0.f;
        #pragma unroll
        for (int i = 0; i < 16; i++) s += __expf(vals[i] - m);
        s += __shfl_xor_sync(0xffffffffu, s, 1);
        s += __shfl_xor_sync(0xffffffffu, s, 2);
        if (part == 0) {
            size_t r = (size_t)brb*64 + hd;
            g_pm[r*NTILES + tile] = m;
            g_ps[r*NTILES + tile] = s;
        }
    }

    // partial ctx
    {
        int h  = tid >> 5;
        int dd = (tid >> 2) & 7;
        int ep = tid & 3;
        float ce0 = 0.f, ce1 = 0.f;
        #pragma unroll 4
        for (int tt = 0; tt < 64; tt++) {
            float  kv = qkvs[tt*QSTR + 64 + h*8 + dd];
            float2 vv = *(const float2*)&qkvs[tt*QSTR + 128 + h*8 + 2*ep];
            ce0 += kv * vv.x;
            ce1 += kv * vv.y;
        }
        float2 r = make_float2(ce0, ce1);
        *(float2*)&g_cpart[((size_t)tile*64 + brb)*512 + h*64 + dd*8 + 2*ep] = r;
    }

    // q scatter
    for (int idx = tid; idx < 4096; idx += 256) {
        int hd = idx >> 6, tt = idx & 63;
        g_q[((size_t)brb*64 + hd)*NPIX + n0 + tt] = qkvs[tt*QSTR + hd];
    }
}

// ---------------- K3a: reduce partial ctx over tiles ------------------------
__global__ void ctx_reduce_kernel()
{
    const int brb = blockIdx.x;
    const int tid = threadIdx.x;
    float s = 0.f;
    const float* p = g_cpart + (size_t)brb*512 + tid;
    #pragma unroll 4
    for (int t = 0; t < NTILES; t++)
        s += p[(size_t)t*64*512];
    g_ctx[(size_t)brb*512 + tid] = s;
}

// ---------------- K3b: combine per-tile q stats ----------------------------
__global__ void qcombine_kernel()
{
    const int r    = blockIdx.x;
    const int lane = threadIdx.x;
    const float* pm = g_pm + (size_t)r*NTILES;
    const float* ps = g_ps + (size_t)r*NTILES;

    float mv[4]; float m = -1e30f;
    #pragma unroll
    for (int j = 0; j < 4; j++) {
        int t = lane + 32*j;
        mv[j] = (t < NTILES) ? pm[t] : -1e30f;
        m = fmaxf(m, mv[j]);
    }
    #pragma unroll
    for (int off = 16; off; off >>= 1)
        m = fmaxf(m, __shfl_xor_sync(0xffffffffu, m, off));

    float s = 0.f;
    #pragma unroll
    for (int j = 0; j < 4; j++) {
        int t = lane + 32*j;
        if (t < NTILES) s += ps[t] * __expf(mv[j] - m);
    }
    #pragma unroll
    for (int off = 16; off; off >>= 1)
        s += __shfl_xor_sync(0xffffffffu, s, off);

    if (lane == 0) { g_qm[r] = m; g_qs[r] = s; }
}

// ---------------- K5: out = softmax(q)@ctx, scrambled reshape, proj, scale --
__global__ void attn_out_kernel(const float* __restrict__ wproj,
                                const float* __restrict__ bproj,
                                const float* __restrict__ scale)
{
    __shared__ float wp   [64*68];
    __shared__ float out_s[32*64];
    __shared__ float p_s  [32*64];
    __shared__ float ctx_s[64];
    __shared__ float m_s[8];
    const int tid = threadIdx.x;
    const int brb = blockIdx.y;
    const int br  = brb >> 4;
    const int g0  = blockIdx.x * 32;
    const int h   = g0 / 800;

    for (int idx = tid; idx < 4096; idx += 256) {
        int o = idx >> 6, f = idx & 63;
        wp[f*68 + o] = wproj[idx];
    }
    if (tid < 64) {
        int d = tid >> 3;
        float invS = 1.f / g_qs[(size_t)brb*64 + h*8 + d];
        ctx_s[tid] = g_ctx[((size_t)brb*NHEADS + h)*64 + tid] * invS;
    }
    if (tid >= 64 && tid < 72) m_s[tid - 64] = g_qm[(size_t)brb*64 + h*8 + (tid - 64)];
    __syncthreads();

    {
        int g = tid >> 3, i = tid & 7;
        int np = g0 + g;
        int n0 = (np % 800) * 8;
        const float* qp = g_q + ((size_t)brb*64 + h*8)*NPIX + n0 + i;
        float oo[8] = {0,0,0,0,0,0,0,0};
        #pragma unroll
        for (int d = 0; d < 8; d++) {
            float qv = __expf(qp[(size_t)d*NPIX] - m_s[d]);
            #pragma unroll
            for (int e = 0; e < 8; e++) oo[e] += qv * ctx_s[d*8 + e];
        }
        #pragma unroll
        for (int e = 0; e < 8; e++) out_s[g*64 + i*8 + e] = oo[e];
    }
    __syncthreads();

    {
        int gp = tid >> 4;
        int o4 = (tid & 15) * 4;
        float p0[4] = {0,0,0,0}, p1[4] = {0,0,0,0};
        #pragma unroll 8
        for (int f = 0; f < 64; f++) {
            float a0 = out_s[(2*gp    )*64 + f];
            float a1 = out_s[(2*gp + 1)*64 + f];
            float4 w4 = *(const float4*)&wp[f*68 + o4];
            p0[0] += a0*w4.x; p0[1] += a0*w4.y; p0[2] += a0*w4.z; p0[3] += a0*w4.w;
            p1[0] += a1*w4.x; p1[1] += a1*w4.y; p1[2] += a1*w4.z; p1[3] += a1*w4.w;
        }
        float scl  = __ldg(&scale[br]);
        float4 bp4 = *(const float4*)&bproj[o4];
        float4 r0, r1;
        r0.x = (p0[0]+bp4.x)*scl; r0.y = (p0[1]+bp4.y)*scl;
        r0.z = (p0[2]+bp4.z)*scl; r0.w = (p0[3]+bp4.w)*scl;
        r1.x = (p1[0]+bp4.x)*scl; r1.y = (p1[1]+bp4.y)*scl;
        r1.z = (p1[2]+bp4.z)*scl; r1.w = (p1[3]+bp4.w)*scl;
        *(float4*)&p_s[(2*gp    )*64 + o4] = r0;
        *(float4*)&p_s[(2*gp + 1)*64 + o4] = r1;
    }
    __syncthreads();

    float* ap = g_att + (size_t)brb*64*NPIX;
    for (int idx = tid; idx < 64*8; idx += 256) {
        int o = idx >> 3, seg = idx & 7;
        float4 r;
        r.x = p_s[(seg*4 + 0)*64 + o];
        r.y = p_s[(seg*4 + 1)*64 + o];
        r.z = p_s[(seg*4 + 2)*64 + o];
        r.w = p_s[(seg*4 + 3)*64 + o];
        *(float4*)&ap[(size_t)o*NPIX + g0 + seg*4] = r;
    }
}

// ---------------- K6: final 256x256 GEMM via mma.sync tf32 ------------------
#define ASTR 36
#define BSTR 72
__global__ void final_kernel(const float* __restrict__ wf,
                             const float* __restrict__ bf,
                             float* __restrict__ out)
{
    __shared__ uint32_t As[256*ASTR];
    __shared__ uint32_t Bs[32*BSTR];
    const int tid = threadIdx.x;
    const int n0  = blockIdx.x * 64;
    const int b   = blockIdx.y;

    const int warp = tid >> 5, lane = tid & 31;
    const int wo = (warp >> 1) * 64;
    const int wn = (warp & 1) * 32;
    const int g = lane >> 2, t = lane & 3;

    float d[4][4][4];
    #pragma unroll
    for (int mf = 0; mf < 4; mf++)
        #pragma unroll
        for (int nf = 0; nf < 4; nf++)
            #pragma unroll
            for (int r = 0; r < 4; r++) d[mf][nf][r] = 0.f;

    for (int kc = 0; kc < 256; kc += 32) {
        #pragma unroll
        for (int it = 0; it < 32; it++) {
            int idx = tid + it*256;
            int o = idx >> 5, k = idx & 31;
            As[o*ASTR + k] = f2tf32(wf[(size_t)o*256 + kc + k]);
        }
        #pragma unroll
        for (int it = 0; it < 8; it++) {
            int idx = tid + it*256;
            int k = idx >> 6, n = idx & 63;
            int kk = kc + k;
            Bs[k*BSTR + n] = f2tf32(
                g_att[(((size_t)(kk >> 6)*NB + b)*64 + (kk & 63))*NPIX + n0 + n]);
        }
        __syncthreads();

        #pragma unroll
        for (int kf = 0; kf < 4; kf++) {
            int k0 = kf*8;
            uint32_t a[4][4];
            #pragma unroll
            for (int mf = 0; mf < 4; mf++) {
                int orow = wo + mf*16 + g;
                a[mf][0] = As[(orow    )*ASTR + k0 + t];
                a[mf][1] = As[(orow + 8)*ASTR + k0 + t];
                a[mf][2] = As[(orow    )*ASTR + k0 + t + 4];
                a[mf][3] = As[(orow + 8)*ASTR + k0 + t + 4];
            }
            uint32_t bb[4][2];
            #pragma unroll
            for (int nf = 0; nf < 4; nf++) {
                int ncol = wn + nf*8 + g;
                bb[nf][0] = Bs[(k0 + t    )*BSTR + ncol];
                bb[nf][1] = Bs[(k0 + t + 4)*BSTR + ncol];
            }
            #pragma unroll
            for (int mf = 0; mf < 4; mf++)
                #pragma unroll
                for (int nf = 0; nf < 4; nf++)
                    mma_tf32(d[mf][nf], a[mf][0], a[mf][1], a[mf][2], a[mf][3],
                             bb[nf][0], bb[nf][1]);
        }
        __syncthreads();
    }

    #pragma unroll
    for (int mf = 0; mf < 4; mf++) {
        int o_lo = wo + mf*16 + g;
        int o_hi = o_lo + 8;
        float bf_lo = __ldg(&bf[o_lo]);
        float bf_hi = __ldg(&bf[o_hi]);
        float* base_lo = &out[((size_t)b*256 + o_lo)*NPIX + n0 + wn];
        float* base_hi = &out[((size_t)b*256 + o_hi)*NPIX + n0 + wn];
        #pragma unroll
        for (int nf = 0; nf < 4; nf++) {
            int nc = nf*8 + 2*t;
            float2 r0 = make_float2(d[mf][nf][0] + bf_lo, d[mf][nf][1] + bf_lo);
            float2 r1 = make_float2(d[mf][nf][2] + bf_hi, d[mf][nf][3] + bf_hi);
            *(float2*)&base_lo[nc] = r0;
            *(float2*)&base_hi[nc] = r1;
        }
    }
}

// ---------------- launch ------------------------------------------------------
extern "C" void kernel_launch(void* const* d_in, const int* in_sizes, int n_in,
                              void* d_out, int out_size)
{
    const float* x     = (const float*)d_in[0];
    const float* w3    = (const float*)d_in[1];
    const float* b3    = (const float*)d_in[2];
    const float* w5    = (const float*)d_in[3];
    const float* b5    = (const float*)d_in[4];
    const float* w7    = (const float*)d_in[5];
    const float* b7    = (const float*)d_in[6];
    const float* w9    = (const float*)d_in[7];
    const float* b9    = (const float*)d_in[8];
    const float* wqkv  = (const float*)d_in[9];
    const float* wproj = (const float*)d_in[10];
    const float* bproj = (const float*)d_in[11];
    const float* wf    = (const float*)d_in[12];
    const float* bf    = (const float*)d_in[13];
    const float* scale = (const float*)d_in[14];
    float* out = (float*)d_out;

    dim3 gconv(5, 64, 16);
    dwconv_kernel<3><<<gconv, 320>>>(x, w3, b3, 0);
    dwconv_kernel<5><<<gconv, 320>>>(x, w5, b5, 1);
    dwconv_kernel<7><<<gconv, 320>>>(x, w7, b7, 2);
    dwconv_kernel<9><<<gconv, 320>>>(x, w9, b9, 3);

    static bool attr_set = false;
    if (!attr_set) {
        cudaFuncSetAttribute(qkv_kernel,
                             cudaFuncAttributeMaxDynamicSharedMemorySize, 72000);
        attr_set = true;
    }
    qkv_kernel<<<dim3(100, 64), 256, 70656>>>(wqkv);
    ctx_reduce_kernel<<<64, 512>>>();
    qcombine_kernel<<<4096, 32>>>();
    attn_out_kernel<<<dim3(200, 64), 256>>>(wproj, bproj, scale);
    final_kernel<<<dim3(100, 16), 256>>>(wf, bf, out);
}

// round 7
// speedup vs baseline: 2.0382x; 1.2386x over previous
#include <cuda_runtime.h>
#include <cstdint>

#define BRANCHES 4
#define NB 16
#define CPB 64
#define HGT 80
#define WID 80
#define NPIX 6400
#define NHEADS 8
#define NTILES 100

// ---------------- scratch ----------------------------------------------------
__device__ float g_y    [(size_t)BRANCHES*NB*CPB*NPIX];   // dwconv out [brb][c][n]
__device__ float g_q    [(size_t)BRANCHES*NB*CPB*NPIX];   // raw q [brb][h*8+d][n]
__device__ float g_ctx  [(size_t)BRANCHES*NB*NHEADS*64];  // ctx [brb][h][d*8+e]
__device__ float g_cpart[(size_t)NTILES*64*512];          // partial ctx [tile][brb][cell]
__device__ float g_pm   [(size_t)4096*NTILES];            // per-tile q max [row][tile]
__device__ float g_ps   [(size_t)4096*NTILES];            // per-tile q sumexp [row][tile]
__device__ float g_qm   [(size_t)4096];                   // global q max per row
__device__ float g_qs   [(size_t)4096];                   // global q sumexp per row
__device__ float g_att  [(size_t)BRANCHES*NB*CPB*NPIX];   // attention out [brb][o][n']

// ---------------- tf32 helpers ----------------------------------------------
__device__ __forceinline__ uint32_t f2tf32(float x) {
    uint32_t r;
    asm("cvt.rna.tf32.f32 %0, %1;" : "=r"(r) : "f"(x));
    return r;
}
__device__ __forceinline__ void mma_tf32(float d[4],
                                         uint32_t a0, uint32_t a1, uint32_t a2, uint32_t a3,
                                         uint32_t b0, uint32_t b1) {
    asm volatile(
        "mma.sync.aligned.m16n8k8.row.col.f32.tf32.tf32.f32 "
        "{%0,%1,%2,%3}, {%4,%5,%6,%7}, {%8,%9}, {%0,%1,%2,%3};"
        : "+f"(d[0]), "+f"(d[1]), "+f"(d[2]), "+f"(d[3])
        : "r"(a0), "r"(a1), "r"(a2), "r"(a3), "r"(b0), "r"(b1));
}
__device__ __forceinline__ void tf32_split(float x, uint32_t& hi, uint32_t& lo) {
    hi = f2tf32(x);
    lo = f2tf32(x - __uint_as_float(hi));
}

// ---------------- K1: depthwise conv + bias + residual + relu ---------------
// grid (5 row-tiles, 64 channels, 16 batch), block 320 = 20x16
template<int KS>
__global__ void dwconv_kernel(const float* __restrict__ x,
                              const float* __restrict__ w,
                              const float* __restrict__ bias,
                              int br)
{
    __shared__ float tile[24*88];
    __shared__ float wsm[KS*KS];
    const int b    = blockIdx.z;
    const int c    = blockIdx.y;
    const int row0 = blockIdx.x * 16;
    const int tid  = threadIdx.x;

    if (tid < KS*KS) wsm[tid] = w[c*KS*KS + tid];
    const float bv = bias[c];
    const float* xp = x + ((size_t)b*256 + (size_t)br*64 + c) * NPIX;

    for (int idx = tid; idx < 24*88; idx += 320) {
        int r  = idx / 88, cl = idx % 88;
        int gh = row0 - 4 + r, gw = cl - 4;
        float v = 0.f;
        if (gh >= 0 && gh < HGT && gw >= 0 && gw < WID) v = xp[gh*WID + gw];
        tile[idx] = v;
    }
    __syncthreads();

    const int tx = tid % 20, ty = tid / 20;
    const int col0 = tx * 4;
    constexpr int PAD = KS / 2;
    constexpr int OFF = 4 - PAD;   // window offset into 12-float aligned row
    float a0 = 0.f, a1 = 0.f, a2 = 0.f, a3 = 0.f;
    float win[12];
    #pragma unroll
    for (int kh = 0; kh < KS; kh++) {
        int rb = (ty + 4 - PAD + kh)*88 + col0;   // 16B-aligned (88,col0 mult of 4)
        float4 w0 = *(const float4*)&tile[rb];
        float4 w1 = *(const float4*)&tile[rb + 4];
        float4 w2 = *(const float4*)&tile[rb + 8];
        win[0]=w0.x; win[1]=w0.y; win[2]=w0.z; win[3]=w0.w;
        win[4]=w1.x; win[5]=w1.y; win[6]=w1.z; win[7]=w1.w;
        win[8]=w2.x; win[9]=w2.y; win[10]=w2.z; win[11]=w2.w;
        #pragma unroll
        for (int kw = 0; kw < KS; kw++) {
            float wv = wsm[kh*KS + kw];
            a0 += win[OFF + kw    ] * wv;
            a1 += win[OFF + kw + 1] * wv;
            a2 += win[OFF + kw + 2] * wv;
            a3 += win[OFF + kw + 3] * wv;
        }
    }
    int cb = (ty + 4)*88 + col0 + 4;
    float4 res = *(const float4*)&tile[cb];
    float* yp = g_y + (((size_t)br*NB + b)*CPB + c)*NPIX + (row0 + ty)*WID + col0;
    float4 r;
    r.x = fmaxf(a0 + bv + res.x, 0.f);
    r.y = fmaxf(a1 + bv + res.y, 0.f);
    r.z = fmaxf(a2 + bv + res.z, 0.f);
    r.w = fmaxf(a3 + bv + res.w, 0.f);
    *(float4*)yp = r;
}

// ---------------- K2: qkv via 3xTF32 MMA + k-softmax + partial ctx/stats ----
// grid (100 token tiles, 64 br*b), block 256 = 8 warps (2 m x 4 n)
#define QSTR 194
#define WQS  68
#define YSS  72
__global__ void qkv_kernel(const float* __restrict__ wqkv)
{
    extern __shared__ float sm[];
    float* wq = sm;                 // [j=192][c] stride WQS
    float* ys = sm + 13056;         // [c=64][t] stride YSS
    const int tid  = threadIdx.x;
    const int brb  = blockIdx.y;
    const int tile = blockIdx.x;
    const int n0   = tile * 64;

    const float* yp = g_y + (size_t)brb * CPB * NPIX;
    // vectorized staging
    for (int idx = tid; idx < 3072; idx += 256) {          // wq: 12288 f = 3072 f4
        int j = idx >> 4, c4 = (idx & 15) * 4;
        float4 v = *(const float4*)&wqkv[j*64 + c4];
        *(float4*)&wq[j*WQS + c4] = v;
    }
    for (int idx = tid; idx < 1024; idx += 256) {          // ys: 4096 f = 1024 f4
        int c = idx >> 4, t4 = (idx & 15) * 4;
        float4 v = *(const float4*)&yp[(size_t)c*NPIX + n0 + t4];
        *(float4*)&ys[c*YSS + t4] = v;
    }
    __syncthreads();

    const int warp = tid >> 5, lane = tid & 31;
    const int wm = (warp >> 2) * 96;
    const int wn = (warp & 3) * 16;
    const int g = lane >> 2, t = lane & 3;

    float d[6][2][4];
    #pragma unroll
    for (int mf = 0; mf < 6; mf++)
        #pragma unroll
        for (int nf = 0; nf < 2; nf++)
            #pragma unroll
            for (int r = 0; r < 4; r++) d[mf][nf][r] = 0.f;

    #pragma unroll
    for (int ks = 0; ks < 8; ks++) {
        const int k0 = ks * 8;
        uint32_t bh[2][2], bl[2][2];
        #pragma unroll
        for (int nf = 0; nf < 2; nf++) {
            int ncol = wn + nf*8 + g;
            tf32_split(ys[(k0 + t    )*YSS + ncol], bh[nf][0], bl[nf][0]);
            tf32_split(ys[(k0 + t + 4)*YSS + ncol], bh[nf][1], bl[nf][1]);
        }
        #pragma unroll
        for (int mf = 0; mf < 6; mf++) {
            int r0 = wm + mf*16 + g;
            uint32_t ah[4], al[4];
            tf32_split(wq[(r0    )*WQS + k0 + t    ], ah[0], al[0]);
            tf32_split(wq[(r0 + 8)*WQS + k0 + t    ], ah[1], al[1]);
            tf32_split(wq[(r0    )*WQS + k0 + t + 4], ah[2], al[2]);
            tf32_split(wq[(r0 + 8)*WQS + k0 + t + 4], ah[3], al[3]);
            #pragma unroll
            for (int nf = 0; nf < 2; nf++) {
                mma_tf32(d[mf][nf], ah[0], ah[1], ah[2], ah[3], bl[nf][0], bl[nf][1]);
                mma_tf32(d[mf][nf], al[0], al[1], al[2], al[3], bh[nf][0], bh[nf][1]);
                mma_tf32(d[mf][nf], ah[0], ah[1], ah[2], ah[3], bh[nf][0], bh[nf][1]);
            }
        }
    }
    __syncthreads();

    float* qkvs = sm;  // [t=64][j stride QSTR]
    #pragma unroll
    for (int mf = 0; mf < 6; mf++) {
        int r0 = wm + mf*16 + g;
        #pragma unroll
        for (int nf = 0; nf < 2; nf++) {
            int c0 = wn + nf*8 + 2*t;
            qkvs[(c0    )*QSTR + r0    ] = d[mf][nf][0];
            qkvs[(c0 + 1)*QSTR + r0    ] = d[mf][nf][1];
            qkvs[(c0    )*QSTR + r0 + 8] = d[mf][nf][2];
            qkvs[(c0 + 1)*QSTR + r0 + 8] = d[mf][nf][3];
        }
    }
    __syncthreads();

    // k softmax over head-dim (8)
    for (int th = tid; th < 512; th += 256) {
        int tt = th & 63, h = th >> 6;
        float* kr = &qkvs[tt*QSTR + 64 + h*8];
        float kv[8];
        #pragma unroll
        for (int dd = 0; dd < 8; dd++) kv[dd] = kr[dd];
        float m = kv[0];
        #pragma unroll
        for (int dd = 1; dd < 8; dd++) m = fmaxf(m, kv[dd]);
        float e[8]; float s = 0.f;
        #pragma unroll
        for (int dd = 0; dd < 8; dd++) { e[dd] = __expf(kv[dd] - m); s += e[dd]; }
        float inv = 1.f / s;
        #pragma unroll
        for (int dd = 0; dd < 8; dd++) kr[dd] = e[dd] * inv;
    }
    __syncthreads();

    // per-tile q stats
    {
        int hd = tid >> 2, part = tid & 3;
        float vals[16];
        #pragma unroll
        for (int i = 0; i < 16; i++) vals[i] = qkvs[(part*16 + i)*QSTR + hd];
        float m = vals[0];
        #pragma unroll
        for (int i = 1; i < 16; i++) m = fmaxf(m, vals[i]);
        m = fmaxf(m, __shfl_xor_sync(0xffffffffu, m, 1));
        m = fmaxf(m, __shfl_xor_sync(0xffffffffu, m, 2));
        float s = 0.f;
        #pragma unroll
        for (int i = 0; i < 16; i++) s += __expf(vals[i] - m);
        s += __shfl_xor_sync(0xffffffffu, s, 1);
        s += __shfl_xor_sync(0xffffffffu, s, 2);
        if (part == 0) {
            size_t r = (size_t)brb*64 + hd;
            g_pm[r*NTILES + tile] = m;
            g_ps[r*NTILES + tile] = s;
        }
    }

    // partial ctx
    {
        int h  = tid >> 5;
        int dd = (tid >> 2) & 7;
        int ep = tid & 3;
        float ce0 = 0.f, ce1 = 0.f;
        #pragma unroll 4
        for (int tt = 0; tt < 64; tt++) {
            float  kv = qkvs[tt*QSTR + 64 + h*8 + dd];
            float2 vv = *(const float2*)&qkvs[tt*QSTR + 128 + h*8 + 2*ep];
            ce0 += kv * vv.x;
            ce1 += kv * vv.y;
        }
        float2 r = make_float2(ce0, ce1);
        *(float2*)&g_cpart[((size_t)tile*64 + brb)*512 + h*64 + dd*8 + 2*ep] = r;
    }

    // q scatter, vectorized stores
    for (int idx = tid; idx < 1024; idx += 256) {
        int hd = idx >> 4, t4 = (idx & 15) * 4;
        float4 v;
        v.x = qkvs[(t4    )*QSTR + hd];
        v.y = qkvs[(t4 + 1)*QSTR + hd];
        v.z = qkvs[(t4 + 2)*QSTR + hd];
        v.w = qkvs[(t4 + 3)*QSTR + hd];
        *(float4*)&g_q[((size_t)brb*64 + hd)*NPIX + n0 + t4] = v;
    }
}

// ---------------- K3a: reduce partial ctx over tiles ------------------------
__global__ void ctx_reduce_kernel()
{
    const int brb = blockIdx.x;
    const int tid = threadIdx.x;
    float s = 0.f;
    const float* p = g_cpart + (size_t)brb*512 + tid;
    #pragma unroll 4
    for (int t = 0; t < NTILES; t++)
        s += p[(size_t)t*64*512];
    g_ctx[(size_t)brb*512 + tid] = s;
}

// ---------------- K3b: combine per-tile q stats ----------------------------
__global__ void qcombine_kernel()
{
    const int r    = blockIdx.x;
    const int lane = threadIdx.x;
    const float* pm = g_pm + (size_t)r*NTILES;
    const float* ps = g_ps + (size_t)r*NTILES;

    float mv[4]; float m = -1e30f;
    #pragma unroll
    for (int j = 0; j < 4; j++) {
        int t = lane + 32*j;
        mv[j] = (t < NTILES) ? pm[t] : -1e30f;
        m = fmaxf(m, mv[j]);
    }
    #pragma unroll
    for (int off = 16; off; off >>= 1)
        m = fmaxf(m, __shfl_xor_sync(0xffffffffu, m, off));

    float s = 0.f;
    #pragma unroll
    for (int j = 0; j < 4; j++) {
        int t = lane + 32*j;
        if (t < NTILES) s += ps[t] * __expf(mv[j] - m);
    }
    #pragma unroll
    for (int off = 16; off; off >>= 1)
        s += __shfl_xor_sync(0xffffffffu, s, off);

    if (lane == 0) { g_qm[r] = m; g_qs[r] = s; }
}

// ---------------- K5: out = softmax(q)@ctx, reshape, proj (tf32 MMA), scale -
// grid (200 group-tiles, 64 br*b), block 256
#define WPS 72
#define OSS 68
__global__ void attn_out_kernel(const float* __restrict__ wproj,
                                const float* __restrict__ bproj,
                                const float* __restrict__ scale)
{
    __shared__ float wp   [64*WPS];   // [f][o]
    __shared__ float out_s[32*OSS];   // [g][f]
    __shared__ float p_s  [32*OSS];   // [g][o]
    __shared__ float ctx_s[64];
    __shared__ float m_s[8];
    const int tid = threadIdx.x;
    const int brb = blockIdx.y;
    const int br  = brb >> 4;
    const int g0  = blockIdx.x * 32;
    const int h   = g0 / 800;

    for (int idx = tid; idx < 4096; idx += 256) {
        int o = idx >> 6, f = idx & 63;
        wp[f*WPS + o] = wproj[idx];
    }
    if (tid < 64) {
        int d = tid >> 3;
        float invS = 1.f / g_qs[(size_t)brb*64 + h*8 + d];
        ctx_s[tid] = g_ctx[((size_t)brb*NHEADS + h)*64 + tid] * invS;
    }
    if (tid >= 64 && tid < 72) m_s[tid - 64] = g_qm[(size_t)brb*64 + h*8 + (tid - 64)];
    __syncthreads();

    // Phase A: out[g][i*8+e] = sum_d exp(q[h,d,n]-m_d) * ctx'[d,e]
    {
        int g = tid >> 3, i = tid & 7;
        int np = g0 + g;
        int n0 = (np % 800) * 8;
        const float* qp = g_q + ((size_t)brb*64 + h*8)*NPIX + n0 + i;
        float oo[8] = {0,0,0,0,0,0,0,0};
        #pragma unroll
        for (int d = 0; d < 8; d++) {
            float qv = __expf(qp[(size_t)d*NPIX] - m_s[d]);
            #pragma unroll
            for (int e = 0; e < 8; e++) oo[e] += qv * ctx_s[d*8 + e];
        }
        #pragma unroll
        for (int e = 0; e < 8; e++) out_s[g*OSS + i*8 + e] = oo[e];
    }
    __syncthreads();

    // Phase B via tf32 MMA: p[g][o] = (sum_f out[g][f]*wp[f][o] + bproj[o])*scl
    // 8 warps: 2 m16-tiles (warp&1) x 4 n16-groups (warp>>1), k=64
    {
        const int warp = tid >> 5, lane = tid & 31;
        const int pmB = (warp & 1) * 16;
        const int pnB = (warp >> 1) * 16;
        const int gq = lane >> 2, tq = lane & 3;
        float dD[2][4] = {{0,0,0,0},{0,0,0,0}};
        #pragma unroll
        for (int ks = 0; ks < 8; ks++) {
            int k0 = ks*8;
            uint32_t a0 = f2tf32(out_s[(pmB+gq  )*OSS + k0+tq  ]);
            uint32_t a1 = f2tf32(out_s[(pmB+gq+8)*OSS + k0+tq  ]);
            uint32_t a2 = f2tf32(out_s[(pmB+gq  )*OSS + k0+tq+4]);
            uint32_t a3 = f2tf32(out_s[(pmB+gq+8)*OSS + k0+tq+4]);
            #pragma unroll
            for (int nf = 0; nf < 2; nf++) {
                int nc = pnB + nf*8 + gq;
                uint32_t b0 = f2tf32(wp[(k0+tq  )*WPS + nc]);
                uint32_t b1 = f2tf32(wp[(k0+tq+4)*WPS + nc]);
                mma_tf32(dD[nf], a0, a1, a2, a3, b0, b1);
            }
        }
        float scl = __ldg(&scale[br]);
        #pragma unroll
        for (int nf = 0; nf < 2; nf++) {
            int c0 = pnB + nf*8 + 2*tq;
            float bp0 = bproj[c0], bp1 = bproj[c0+1];
            float2 lo = make_float2((dD[nf][0] + bp0)*scl, (dD[nf][1] + bp1)*scl);
            float2 hi = make_float2((dD[nf][2] + bp0)*scl, (dD[nf][3] + bp1)*scl);
            *(float2*)&p_s[(pmB+gq  )*OSS + c0] = lo;
            *(float2*)&p_s[(pmB+gq+8)*OSS + c0] = hi;
        }
    }
    __syncthreads();

    float* ap = g_att + (size_t)brb*64*NPIX;
    for (int idx = tid; idx < 64*8; idx += 256) {
        int o = idx >> 3, seg = idx & 7;
        float4 r;
        r.x = p_s[(seg*4 + 0)*OSS + o];
        r.y = p_s[(seg*4 + 1)*OSS + o];
        r.z = p_s[(seg*4 + 2)*OSS + o];
        r.w = p_s[(seg*4 + 3)*OSS + o];
        *(float4*)&ap[(size_t)o*NPIX + g0 + seg*4] = r;
    }
}

// ---------------- K6: final 256x256 GEMM via mma.sync tf32 ------------------
#define ASTR 36
#define BSTR 72
__global__ void final_kernel(const float* __restrict__ wf,
                             const float* __restrict__ bf,
                             float* __restrict__ out)
{
    __shared__ uint32_t As[256*ASTR];
    __shared__ uint32_t Bs[32*BSTR];
    const int tid = threadIdx.x;
    const int n0  = blockIdx.x * 64;
    const int b   = blockIdx.y;

    const int warp = tid >> 5, lane = tid & 31;
    const int wo = (warp >> 1) * 64;
    const int wn = (warp & 1) * 32;
    const int g = lane >> 2, t = lane & 3;

    float d[4][4][4];
    #pragma unroll
    for (int mf = 0; mf < 4; mf++)
        #pragma unroll
        for (int nf = 0; nf < 4; nf++)
            #pragma unroll
            for (int r = 0; r < 4; r++) d[mf][nf][r] = 0.f;

    for (int kc = 0; kc < 256; kc += 32) {
        // A: 8192 f = 2048 f4
        #pragma unroll
        for (int it = 0; it < 8; it++) {
            int idx = tid + it*256;
            int o = idx >> 3, k4 = (idx & 7) * 4;
            float4 v = *(const float4*)&wf[(size_t)o*256 + kc + k4];
            uint4 u = make_uint4(f2tf32(v.x), f2tf32(v.y), f2tf32(v.z), f2tf32(v.w));
            *(uint4*)&As[o*ASTR + k4] = u;
        }
        // B: 2048 f = 512 f4
        #pragma unroll
        for (int it = 0; it < 2; it++) {
            int idx = tid + it*256;
            int k = idx >> 4, n4 = (idx & 15) * 4;
            int kk = kc + k;
            float4 v = *(const float4*)&g_att[
                (((size_t)(kk >> 6)*NB + b)*64 + (kk & 63))*NPIX + n0 + n4];
            uint4 u = make_uint4(f2tf32(v.x), f2tf32(v.y), f2tf32(v.z), f2tf32(v.w));
            *(uint4*)&Bs[k*BSTR + n4] = u;
        }
        __syncthreads();

        #pragma unroll
        for (int kf = 0; kf < 4; kf++) {
            int k0 = kf*8;
            uint32_t a[4][4];
            #pragma unroll
            for (int mf = 0; mf < 4; mf++) {
                int orow = wo + mf*16 + g;
                a[mf][0] = As[(orow    )*ASTR + k0 + t];
                a[mf][1] = As[(orow + 8)*ASTR + k0 + t];
                a[mf][2] = As[(orow    )*ASTR + k0 + t + 4];
                a[mf][3] = As[(orow + 8)*ASTR + k0 + t + 4];
            }
            uint32_t bb[4][2];
            #pragma unroll
            for (int nf = 0; nf < 4; nf++) {
                int ncol = wn + nf*8 + g;
                bb[nf][0] = Bs[(k0 + t    )*BSTR + ncol];
                bb[nf][1] = Bs[(k0 + t + 4)*BSTR + ncol];
            }
            #pragma unroll
            for (int mf = 0; mf < 4; mf++)
                #pragma unroll
                for (int nf = 0; nf < 4; nf++)
                    mma_tf32(d[mf][nf], a[mf][0], a[mf][1], a[mf][2], a[mf][3],
                             bb[nf][0], bb[nf][1]);
        }
        __syncthreads();
    }

    #pragma unroll
    for (int mf = 0; mf < 4; mf++) {
        int o_lo = wo + mf*16 + g;
        int o_hi = o_lo + 8;
        float bf_lo = __ldg(&bf[o_lo]);
        float bf_hi = __ldg(&bf[o_hi]);
        float* base_lo = &out[((size_t)b*256 + o_lo)*NPIX + n0 + wn];
        float* base_hi = &out[((size_t)b*256 + o_hi)*NPIX + n0 + wn];
        #pragma unroll
        for (int nf = 0; nf < 4; nf++) {
            int nc = nf*8 + 2*t;
            float2 r0 = make_float2(d[mf][nf][0] + bf_lo, d[mf][nf][1] + bf_lo);
            float2 r1 = make_float2(d[mf][nf][2] + bf_hi, d[mf][nf][3] + bf_hi);
            *(float2*)&base_lo[nc] = r0;
            *(float2*)&base_hi[nc] = r1;
        }
    }
}

// ---------------- launch ------------------------------------------------------
extern "C" void kernel_launch(void* const* d_in, const int* in_sizes, int n_in,
                              void* d_out, int out_size)
{
    const float* x     = (const float*)d_in[0];
    const float* w3    = (const float*)d_in[1];
    const float* b3    = (const float*)d_in[2];
    const float* w5    = (const float*)d_in[3];
    const float* b5    = (const float*)d_in[4];
    const float* w7    = (const float*)d_in[5];
    const float* b7    = (const float*)d_in[6];
    const float* w9    = (const float*)d_in[7];
    const float* b9    = (const float*)d_in[8];
    const float* wqkv  = (const float*)d_in[9];
    const float* wproj = (const float*)d_in[10];
    const float* bproj = (const float*)d_in[11];
    const float* wf    = (const float*)d_in[12];
    const float* bf    = (const float*)d_in[13];
    const float* scale = (const float*)d_in[14];
    float* out = (float*)d_out;

    dim3 gconv(5, 64, 16);
    dwconv_kernel<3><<<gconv, 320>>>(x, w3, b3, 0);
    dwconv_kernel<5><<<gconv, 320>>>(x, w5, b5, 1);
    dwconv_kernel<7><<<gconv, 320>>>(x, w7, b7, 2);
    dwconv_kernel<9><<<gconv, 320>>>(x, w9, b9, 3);

    static bool attr_set = false;
    if (!attr_set) {
        cudaFuncSetAttribute(qkv_kernel,
                             cudaFuncAttributeMaxDynamicSharedMemorySize, 72000);
        attr_set = true;
    }
    qkv_kernel<<<dim3(100, 64), 256, 70656>>>(wqkv);
    ctx_reduce_kernel<<<64, 512>>>();
    qcombine_kernel<<<4096, 32>>>();
    attn_out_kernel<<<dim3(200, 64), 256>>>(wproj, bproj, scale);
    final_kernel<<<dim3(100, 16), 256>>>(wf, bf, out);
}